// round 5
// baseline (speedup 1.0000x reference)
#include <cuda_runtime.h>
#include <cuda_bf16.h>
#include <cstdint>

using bf16 = __nv_bfloat16;

namespace {
constexpr int B_  = 4;
constexpr int S_  = 2048;
constexpr int D_  = 1024;
constexpr int H_  = 16;
constexpr int M_  = B_ * S_;  // 8192
constexpr long long OUT_ELEMS  = (long long)M_ * D_;
constexpr long long ATTN_ELEMS = (long long)B_ * H_ * S_ * S_;
constexpr float SHIFT = 10.0f;
}

// ------------------------- device scratch (no allocs) -----------------------
__device__ bf16 g_ahi[M_ * D_], g_alo[M_ * D_];
__device__ bf16 g_qh[M_ * D_],  g_ql[M_ * D_];
__device__ bf16 g_kh[M_ * D_],  g_kl[M_ * D_];
__device__ bf16 g_vh[M_ * D_],  g_vl[M_ * D_];
__device__ bf16 g_ch[M_ * D_],  g_cl[M_ * D_];
__device__ bf16 g_wqh[D_ * D_], g_wql[D_ * D_];
__device__ bf16 g_wkh[D_ * D_], g_wkl[D_ * D_];
__device__ bf16 g_wvh[D_ * D_], g_wvl[D_ * D_];
__device__ bf16 g_woh[D_ * D_], g_wol[D_ * D_];

// ----------------------------- helpers --------------------------------------
__device__ __forceinline__ uint32_t smem_u32(const void* p) {
    uint32_t a;
    asm("{ .reg .u64 t; cvta.to.shared.u64 t, %1; cvt.u32.u64 %0, t; }"
        : "=r"(a) : "l"(p));
    return a;
}

__device__ __forceinline__ void cp16(uint32_t s, const void* g) {
    asm volatile("cp.async.cg.shared.global [%0], [%1], 16;" :: "r"(s), "l"(g));
}
#define CP_COMMIT asm volatile("cp.async.commit_group;" ::: "memory")
#define CP_WAIT0  asm volatile("cp.async.wait_group 0;" ::: "memory")
#define CP_WAIT1  asm volatile("cp.async.wait_group 1;" ::: "memory")

#define LDSM_X4(r0, r1, r2, r3, addr) \
    asm volatile("ldmatrix.sync.aligned.m8n8.x4.shared.b16 {%0,%1,%2,%3}, [%4];" \
                 : "=r"(r0), "=r"(r1), "=r"(r2), "=r"(r3) : "r"(addr))

#define LDSM_X2T(r0, r1, addr) \
    asm volatile("ldmatrix.sync.aligned.m8n8.x2.trans.shared.b16 {%0,%1}, [%2];" \
                 : "=r"(r0), "=r"(r1) : "r"(addr))

__device__ __forceinline__ void mma16816(float c[4], const uint32_t a[4],
                                         uint32_t b0, uint32_t b1) {
    asm volatile(
        "mma.sync.aligned.m16n8k16.row.col.f32.bf16.bf16.f32 "
        "{%0,%1,%2,%3}, {%4,%5,%6,%7}, {%8,%9}, {%0,%1,%2,%3};"
        : "+f"(c[0]), "+f"(c[1]), "+f"(c[2]), "+f"(c[3])
        : "r"(a[0]), "r"(a[1]), "r"(a[2]), "r"(a[3]), "r"(b0), "r"(b1));
}

__device__ __forceinline__ uint32_t pack2(float x, float y) {
    __nv_bfloat162 t = __floats2bfloat162_rn(x, y);
    return *reinterpret_cast<uint32_t*>(&t);
}

// ---------------------------------------------------------------------------
__global__ void split_kernel(const float* __restrict__ x,
                             bf16* __restrict__ hi, bf16* __restrict__ lo, int n)
{
    int i = blockIdx.x * blockDim.x + threadIdx.x;
    if (i < n) {
        float v = x[i];
        bf16 h = __float2bfloat16(v);
        hi[i] = h;
        lo[i] = __float2bfloat16(v - __bfloat162float(h));
    }
}

// ---------------------------------------------------------------------------
// Split-bf16 HMMA GEMM, 128x128 tile, 3-stage cp.async pipeline, ldmatrix.
// ---------------------------------------------------------------------------
struct GemmArgs {
    const bf16 *Ahi, *Alo, *Wh, *Wl;
    const float* bias;
    float* Cf;
    bf16 *Ch, *Cl;
};
struct GemmArgs3 { GemmArgs a[3]; };

__global__ void __launch_bounds__(256, 2) gemm_mma_kernel(GemmArgs3 args)
{
    constexpr int PA = 40;
    constexpr int BUFE = 128 * PA;
    extern __shared__ __align__(16) bf16 gsm[];

    const GemmArgs ga = args.a[blockIdx.z];

    const int tid = threadIdx.x;
    const int w = tid >> 5, lane = tid & 31, gid = lane >> 2, tig = lane & 3;
    const int bm = blockIdx.y * 128, bn = blockIdx.x * 128;
    const int m0 = (w >> 1) * 32, n0 = (w & 1) * 64;

    const bf16* Asrc[3] = {ga.Ahi, ga.Alo, ga.Ahi};
    const bf16* Wsrc[3] = {ga.Wh,  ga.Wh,  ga.Wl};

    float c[2][8][4] = {};

    auto load_chunk = [&](int t, int buf) {
        int seg = t >> 5, kc = (t & 31) << 5;
        const bf16* As = Asrc[seg];
        const bf16* Ws = Wsrc[seg];
        bf16* sAb = gsm + buf * (2 * BUFE);
        bf16* sBb = sAb + BUFE;
#pragma unroll
        for (int i = 0; i < 2; ++i) {
            int idx = tid * 2 + i;
            int row = idx >> 2, q = idx & 3;
            cp16(smem_u32(&sAb[row * PA + q * 8]),
                 As + (size_t)(bm + row) * 1024 + kc + q * 8);
            cp16(smem_u32(&sBb[row * PA + q * 8]),
                 Ws + (size_t)(bn + row) * 1024 + kc + q * 8);
        }
    };

    load_chunk(0, 0); CP_COMMIT;
    load_chunk(1, 1); CP_COMMIT;

    for (int t = 0; t < 96; ++t) {
        if (t + 2 < 96) { CP_WAIT1; } else { CP_WAIT0; }
        __syncthreads();
        if (t + 2 < 96) { load_chunk(t + 2, (t + 2) % 3); CP_COMMIT; }

        const bf16* sAb = gsm + (t % 3) * (2 * BUFE);
        const bf16* sBb = sAb + BUFE;

#pragma unroll
        for (int ks = 0; ks < 32; ks += 16) {
            uint32_t a[2][4];
#pragma unroll
            for (int mi = 0; mi < 2; ++mi) {
                uint32_t ad = smem_u32(
                    &sAb[(m0 + mi * 16 + (lane & 15)) * PA + ks + ((lane >> 4) << 3)]);
                LDSM_X4(a[mi][0], a[mi][1], a[mi][2], a[mi][3], ad);
            }
#pragma unroll
            for (int p = 0; p < 4; ++p) {
                int nbase = n0 + p * 16;
                int br = nbase + (lane & 7) + ((lane >> 4) << 3);
                int bc = ks + (((lane >> 3) & 1) << 3);
                uint32_t b0, b1, b2, b3;
                LDSM_X4(b0, b1, b2, b3, smem_u32(&sBb[br * PA + bc]));
                mma16816(c[0][2 * p],     a[0], b0, b1);
                mma16816(c[1][2 * p],     a[1], b0, b1);
                mma16816(c[0][2 * p + 1], a[0], b2, b3);
                mma16816(c[1][2 * p + 1], a[1], b2, b3);
            }
        }
        __syncthreads();
    }

#pragma unroll
    for (int mi = 0; mi < 2; ++mi) {
#pragma unroll
        for (int ni = 0; ni < 8; ++ni) {
            int r0 = bm + m0 + mi * 16 + gid;
            int col = bn + n0 + ni * 8 + 2 * tig;
            float bv0 = ga.bias[col], bv1 = ga.bias[col + 1];
            float o00 = c[mi][ni][0] + bv0, o01 = c[mi][ni][1] + bv1;
            float o10 = c[mi][ni][2] + bv0, o11 = c[mi][ni][3] + bv1;
            if (ga.Cf) {
                *(float2*)&ga.Cf[(size_t)r0 * 1024 + col] = make_float2(o00, o01);
                *(float2*)&ga.Cf[(size_t)(r0 + 8) * 1024 + col] = make_float2(o10, o11);
            }
            if (ga.Ch) {
                float h00 = __bfloat162float(__float2bfloat16(o00));
                float h01 = __bfloat162float(__float2bfloat16(o01));
                float h10 = __bfloat162float(__float2bfloat16(o10));
                float h11 = __bfloat162float(__float2bfloat16(o11));
                *(uint32_t*)&ga.Ch[(size_t)r0 * 1024 + col]       = pack2(o00, o01);
                *(uint32_t*)&ga.Ch[(size_t)(r0 + 8) * 1024 + col] = pack2(o10, o11);
                *(uint32_t*)&ga.Cl[(size_t)r0 * 1024 + col]       = pack2(o00 - h00, o01 - h01);
                *(uint32_t*)&ga.Cl[(size_t)(r0 + 8) * 1024 + col] = pack2(o10 - h10, o11 - h11);
            }
        }
    }
}

// ---------------------------------------------------------------------------
// Two-phase flash attention (HMMA, register-resident P):
//  Phase 1: l[row] = sum_k exp(s - SHIFT)       (S via 3-pass split MMA)
//  Phase 2: recompute S, p = exp(s - SHIFT)/l, write attn (normalized),
//           ctx += p @ V (3-pass, P in registers via C->A frag repack),
//           write ctx as bf16 hi/lo.
//  Warp layout: 8 warps x 16 q-rows; each warp covers all 64 keys / 64 dk.
// ---------------------------------------------------------------------------
__global__ void __launch_bounds__(256) attn_mma_kernel(
    const bf16* __restrict__ qh, const bf16* __restrict__ ql,
    const bf16* __restrict__ kh, const bf16* __restrict__ kl,
    const bf16* __restrict__ vh, const bf16* __restrict__ vl,
    const int* __restrict__ maskg,
    float* __restrict__ attn,
    bf16* __restrict__ ctxh, bf16* __restrict__ ctxl)
{
    constexpr int P = 72;
    constexpr int KVBUF = 4 * 64 * P;   // 18432 bf16 per stage (KH,KL,VH,VL)
    extern __shared__ __align__(16) bf16 dsm[];
    bf16* QH  = dsm;                      // 128*72
    bf16* QL  = dsm + 9216;
    bf16* KV0 = dsm + 18432;              // 2 stages
    int*   sMask = (int*)(dsm + 18432 + 2 * KVBUF);  // 2048 ints (full row)
    float* sL    = (float*)(sMask + 2048);           // 128 floats

    const int tid = threadIdx.x;
    const int w = tid >> 5, lane = tid & 31, gid = lane >> 2, tig = lane & 3;
    const int qt = blockIdx.x, h = blockIdx.y, b = blockIdx.z;
    const int q0 = qt * 128;
    const int m0 = w * 16;

    // ---- load Q hi/lo + full mask row (group 0) ----
    {
        size_t base = (size_t)(b * S_ + q0) * D_ + h * 64;
#pragma unroll
        for (int i = 0; i < 4; ++i) {
            int idx = tid * 4 + i;
            int row = idx >> 3, qq = idx & 7;
            cp16(smem_u32(&QH[row * P + qq * 8]), qh + base + (size_t)row * D_ + qq * 8);
            cp16(smem_u32(&QL[row * P + qq * 8]), ql + base + (size_t)row * D_ + qq * 8);
        }
#pragma unroll
        for (int i = 0; i < 2; ++i) {
            int j = tid * 2 + i;   // 0..511 quads of ints
            cp16(smem_u32(&sMask[j * 4]), maskg + b * S_ + j * 4);
        }
        CP_COMMIT;
    }

    auto load_k = [&](int kt, int buf) {
        size_t kbase = (size_t)(b * S_ + kt * 64) * D_ + h * 64;
        bf16* KH_ = KV0 + buf * KVBUF;
        bf16* KL_ = KH_ + 4608;
#pragma unroll
        for (int i = 0; i < 2; ++i) {
            int idx = tid * 2 + i;
            int row = idx >> 3, qq = idx & 7;
            size_t go = kbase + (size_t)row * D_ + qq * 8;
            cp16(smem_u32(&KH_[row * P + qq * 8]), kh + go);
            cp16(smem_u32(&KL_[row * P + qq * 8]), kl + go);
        }
    };
    auto load_kv = [&](int kt, int buf) {
        size_t kbase = (size_t)(b * S_ + kt * 64) * D_ + h * 64;
        bf16* KH_ = KV0 + buf * KVBUF;
        bf16* KL_ = KH_ + 4608;
        bf16* VH_ = KH_ + 9216;
        bf16* VL_ = KH_ + 13824;
#pragma unroll
        for (int i = 0; i < 2; ++i) {
            int idx = tid * 2 + i;
            int row = idx >> 3, qq = idx & 7;
            size_t go = kbase + (size_t)row * D_ + qq * 8;
            cp16(smem_u32(&KH_[row * P + qq * 8]), kh + go);
            cp16(smem_u32(&KL_[row * P + qq * 8]), kl + go);
            cp16(smem_u32(&VH_[row * P + qq * 8]), vh + go);
            cp16(smem_u32(&VL_[row * P + qq * 8]), vl + go);
        }
    };

    // S = Q @ K^T for this warp's 16 rows x 64 keys (3 split passes)
    auto computeS = [&](const bf16* KH_, const bf16* KL_, float sc[8][4]) {
        const bf16* Ab[3] = {QH, QL, QH};
        const bf16* Bb[3] = {KH_, KH_, KL_};
#pragma unroll
        for (int ps = 0; ps < 3; ++ps) {
            const bf16* Q_ = Ab[ps];
            const bf16* K_ = Bb[ps];
#pragma unroll
            for (int ks = 0; ks < 64; ks += 16) {
                uint32_t a[4];
                LDSM_X4(a[0], a[1], a[2], a[3],
                        smem_u32(&Q_[(m0 + (lane & 15)) * P + ks + ((lane >> 4) << 3)]));
#pragma unroll
                for (int p = 0; p < 4; ++p) {
                    int br = p * 16 + (lane & 7) + ((lane >> 4) << 3);
                    int bc = ks + (((lane >> 3) & 1) << 3);
                    uint32_t b0, b1, b2, b3;
                    LDSM_X4(b0, b1, b2, b3, smem_u32(&K_[br * P + bc]));
                    mma16816(sc[2 * p],     a, b0, b1);
                    mma16816(sc[2 * p + 1], a, b2, b3);
                }
            }
        }
    };

    // ================= phase 1: l =================
    load_k(0, 0); CP_COMMIT;
    float lacc0 = 0.f, lacc1 = 0.f;

    for (int kt = 0; kt < 32; ++kt) {
        const int buf = kt & 1;
        if (kt + 1 < 32) { load_k(kt + 1, buf ^ 1); CP_COMMIT; CP_WAIT1; }
        else             { CP_WAIT0; }
        __syncthreads();

        const bf16* KH_ = KV0 + buf * KVBUF;
        const bf16* KL_ = KH_ + 4608;

        float sc[8][4] = {};
        computeS(KH_, KL_, sc);

        const int* mk = sMask + kt * 64;
#pragma unroll
        for (int ni = 0; ni < 8; ++ni) {
            int cc = ni * 8 + 2 * tig;
            bool k0 = mk[cc] != 0, k1 = mk[cc + 1] != 0;
            float e00 = k0 ? __expf(sc[ni][0] * 0.125f - SHIFT) : 0.f;
            float e01 = k1 ? __expf(sc[ni][1] * 0.125f - SHIFT) : 0.f;
            float e10 = k0 ? __expf(sc[ni][2] * 0.125f - SHIFT) : 0.f;
            float e11 = k1 ? __expf(sc[ni][3] * 0.125f - SHIFT) : 0.f;
            lacc0 += e00 + e01;
            lacc1 += e10 + e11;
        }
        __syncthreads();
    }

    // reduce over the 4 lanes of each row group; each warp owns distinct rows
    lacc0 += __shfl_xor_sync(0xffffffffu, lacc0, 1);
    lacc0 += __shfl_xor_sync(0xffffffffu, lacc0, 2);
    lacc1 += __shfl_xor_sync(0xffffffffu, lacc1, 1);
    lacc1 += __shfl_xor_sync(0xffffffffu, lacc1, 2);
    if (tig == 0) {
        sL[m0 + gid]     = lacc0;
        sL[m0 + gid + 8] = lacc1;
    }
    __syncthreads();

    float l0 = sL[m0 + gid], l1 = sL[m0 + gid + 8];
    const float invl0 = (l0 > 0.f) ? (1.f / l0) : 0.f;
    const float invl1 = (l1 > 0.f) ? (1.f / l1) : 0.f;

    // ================= phase 2: attn + ctx =================
    load_kv(0, 0); CP_COMMIT;

    float ctxc[8][4] = {};

    for (int kt = 0; kt < 32; ++kt) {
        const int kb = kt * 64;
        const int buf = kt & 1;
        if (kt + 1 < 32) { load_kv(kt + 1, buf ^ 1); CP_COMMIT; CP_WAIT1; }
        else             { CP_WAIT0; }
        __syncthreads();

        const bf16* KH_ = KV0 + buf * KVBUF;
        const bf16* KL_ = KH_ + 4608;
        const bf16* VH_ = KH_ + 9216;
        const bf16* VL_ = KH_ + 13824;

        float sc[8][4] = {};
        computeS(KH_, KL_, sc);

        const int* mk = sMask + kt * 64;
        uint32_t ah[4][4], al[4][4];
#pragma unroll
        for (int ni = 0; ni < 8; ++ni) {
            int cc = ni * 8 + 2 * tig;
            bool k0 = mk[cc] != 0, k1 = mk[cc + 1] != 0;
            float p00 = k0 ? (__expf(sc[ni][0] * 0.125f - SHIFT) * invl0) : 0.f;
            float p01 = k1 ? (__expf(sc[ni][1] * 0.125f - SHIFT) * invl0) : 0.f;
            float p10 = k0 ? (__expf(sc[ni][2] * 0.125f - SHIFT) * invl1) : 0.f;
            float p11 = k1 ? (__expf(sc[ni][3] * 0.125f - SHIFT) * invl1) : 0.f;

            if (attn) {
                size_t arow = ((size_t)((b * H_ + h) * S_) + q0 + m0 + gid) * S_ + kb + cc;
                *(float2*)&attn[arow]                  = make_float2(p00, p01);
                *(float2*)&attn[arow + 8 * (size_t)S_] = make_float2(p10, p11);
            }

            // C-frag -> A-frag repack (hi + residual)
            float h00 = __bfloat162float(__float2bfloat16(p00));
            float h01 = __bfloat162float(__float2bfloat16(p01));
            float h10 = __bfloat162float(__float2bfloat16(p10));
            float h11 = __bfloat162float(__float2bfloat16(p11));
            int t = ni >> 1, base = (ni & 1) * 2;
            ah[t][base]     = pack2(p00, p01);
            ah[t][base + 1] = pack2(p10, p11);
            al[t][base]     = pack2(p00 - h00, p01 - h01);
            al[t][base + 1] = pack2(p10 - h10, p11 - h11);
        }

        // ctx += P @ V  (hh + lh + hl)
#pragma unroll
        for (int t = 0; t < 4; ++t) {
#pragma unroll
            for (int ni = 0; ni < 8; ++ni) {
                uint32_t bh0, bh1, bl0, bl1;
                LDSM_X2T(bh0, bh1,
                         smem_u32(&VH_[(t * 16 + (lane & 15)) * P + ni * 8]));
                LDSM_X2T(bl0, bl1,
                         smem_u32(&VL_[(t * 16 + (lane & 15)) * P + ni * 8]));
                mma16816(ctxc[ni], ah[t], bh0, bh1);
                mma16816(ctxc[ni], al[t], bh0, bh1);
                mma16816(ctxc[ni], ah[t], bl0, bl1);
            }
        }
        __syncthreads();
    }

    // ---- ctx write (normalized, bf16 hi/lo) ----
#pragma unroll
    for (int ni = 0; ni < 8; ++ni) {
        int r = q0 + m0 + gid;
        int col = h * 64 + ni * 8 + 2 * tig;
        size_t base = ((size_t)(b * S_) + r) * D_ + col;
        float o00 = ctxc[ni][0], o01 = ctxc[ni][1];
        float o10 = ctxc[ni][2], o11 = ctxc[ni][3];
        float h00 = __bfloat162float(__float2bfloat16(o00));
        float h01 = __bfloat162float(__float2bfloat16(o01));
        float h10 = __bfloat162float(__float2bfloat16(o10));
        float h11 = __bfloat162float(__float2bfloat16(o11));
        *(uint32_t*)&ctxh[base]                = pack2(o00, o01);
        *(uint32_t*)&ctxh[base + 8 * (size_t)D_] = pack2(o10, o11);
        *(uint32_t*)&ctxl[base]                = pack2(o00 - h00, o01 - h01);
        *(uint32_t*)&ctxl[base + 8 * (size_t)D_] = pack2(o10 - h10, o11 - h11);
    }
}

// ---------------------------------------------------------------------------
extern "C" void kernel_launch(void* const* d_in, const int* in_sizes, int n_in,
                              void* d_out, int out_size)
{
    const float* hs   = (const float*)d_in[0];
    const int*   mask = (const int*)  d_in[1];
    const float* Wq   = (const float*)d_in[2];
    const float* bq   = (const float*)d_in[3];
    const float* Wk   = (const float*)d_in[4];
    const float* bk   = (const float*)d_in[5];
    const float* Wv   = (const float*)d_in[6];
    const float* bv   = (const float*)d_in[7];
    const float* Wo   = (const float*)d_in[8];
    const float* bo   = (const float*)d_in[9];

    float* outp = (float*)d_out;

    bf16 *ahi, *alo, *qhp, *qlp, *khp, *klp, *vhp, *vlp, *chp, *clp;
    bf16 *wqh, *wql, *wkh, *wkl, *wvh, *wvl, *woh, *wol;
    cudaGetSymbolAddress((void**)&ahi,  g_ahi);
    cudaGetSymbolAddress((void**)&alo,  g_alo);
    cudaGetSymbolAddress((void**)&qhp,  g_qh);
    cudaGetSymbolAddress((void**)&qlp,  g_ql);
    cudaGetSymbolAddress((void**)&khp,  g_kh);
    cudaGetSymbolAddress((void**)&klp,  g_kl);
    cudaGetSymbolAddress((void**)&vhp,  g_vh);
    cudaGetSymbolAddress((void**)&vlp,  g_vl);
    cudaGetSymbolAddress((void**)&chp,  g_ch);
    cudaGetSymbolAddress((void**)&clp,  g_cl);
    cudaGetSymbolAddress((void**)&wqh,  g_wqh);
    cudaGetSymbolAddress((void**)&wql,  g_wql);
    cudaGetSymbolAddress((void**)&wkh,  g_wkh);
    cudaGetSymbolAddress((void**)&wkl,  g_wkl);
    cudaGetSymbolAddress((void**)&wvh,  g_wvh);
    cudaGetSymbolAddress((void**)&wvl,  g_wvl);
    cudaGetSymbolAddress((void**)&woh,  g_woh);
    cudaGetSymbolAddress((void**)&wol,  g_wol);

    float* attnp = nullptr;
    if ((long long)out_size >= OUT_ELEMS + ATTN_ELEMS)
        attnp = outp + OUT_ELEMS;

    // 1. splits
    split_kernel<<<(M_ * D_ + 255) / 256, 256>>>(hs, ahi, alo, M_ * D_);
    split_kernel<<<(D_ * D_ + 255) / 256, 256>>>(Wq, wqh, wql, D_ * D_);
    split_kernel<<<(D_ * D_ + 255) / 256, 256>>>(Wk, wkh, wkl, D_ * D_);
    split_kernel<<<(D_ * D_ + 255) / 256, 256>>>(Wv, wvh, wvl, D_ * D_);
    split_kernel<<<(D_ * D_ + 255) / 256, 256>>>(Wo, woh, wol, D_ * D_);

    const int gemm_smem = 3 * 2 * 128 * 40 * (int)sizeof(bf16);   // 61440
    cudaFuncSetAttribute(gemm_mma_kernel,
                         cudaFuncAttributeMaxDynamicSharedMemorySize, gemm_smem);

    // 2. fused Q/K/V projections
    {
        GemmArgs3 a3;
        a3.a[0] = {ahi, alo, wqh, wql, bq, nullptr, qhp, qlp};
        a3.a[1] = {ahi, alo, wkh, wkl, bk, nullptr, khp, klp};
        a3.a[2] = {ahi, alo, wvh, wvl, bv, nullptr, vhp, vlp};
        dim3 gg(D_ / 128, M_ / 128, 3);
        gemm_mma_kernel<<<gg, 256, gemm_smem>>>(a3);
    }

    // 3. two-phase flash attention (normalized attn + bf16 ctx out)
    {
        dim3 ga(S_ / 128, H_, B_);
        int smA = (18432 + 2 * 18432) * (int)sizeof(bf16)
                  + 2048 * (int)sizeof(int) + 128 * (int)sizeof(float);  // 119296
        cudaFuncSetAttribute(attn_mma_kernel,
                             cudaFuncAttributeMaxDynamicSharedMemorySize, smA);
        attn_mma_kernel<<<ga, 256, smA>>>(qhp, qlp, khp, klp, vhp, vlp, mask,
                                          attnp, chp, clp);
    }

    // 4. output projection (f32 out + bias)
    {
        GemmArgs3 a3;
        a3.a[0] = {chp, clp, woh, wol, bo, outp, nullptr, nullptr};
        dim3 gg(D_ / 128, M_ / 128, 1);
        gemm_mma_kernel<<<gg, 256, gemm_smem>>>(a3);
    }
}

// round 6
// speedup vs baseline: 1.4225x; 1.4225x over previous
#include <cuda_runtime.h>
#include <cuda_bf16.h>
#include <cuda_fp16.h>
#include <cstdint>

using bf16 = __nv_bfloat16;

namespace {
constexpr int B_  = 4;
constexpr int S_  = 2048;
constexpr int D_  = 1024;
constexpr int H_  = 16;
constexpr int M_  = B_ * S_;  // 8192
constexpr long long OUT_ELEMS  = (long long)M_ * D_;
constexpr long long ATTN_ELEMS = (long long)B_ * H_ * S_ * S_;
}

// ------------------------- device scratch (no allocs) -----------------------
__device__ bf16 g_ahi[M_ * D_], g_alo[M_ * D_];
__device__ half g_qf[M_ * D_], g_kf[M_ * D_], g_vf[M_ * D_];
__device__ bf16 g_ch[M_ * D_],  g_cl[M_ * D_];
__device__ bf16 g_wqh[D_ * D_], g_wql[D_ * D_];
__device__ bf16 g_wkh[D_ * D_], g_wkl[D_ * D_];
__device__ bf16 g_wvh[D_ * D_], g_wvl[D_ * D_];
__device__ bf16 g_woh[D_ * D_], g_wol[D_ * D_];
__device__ float g_lrow[B_ * H_ * S_];

// ----------------------------- helpers --------------------------------------
__device__ __forceinline__ uint32_t smem_u32(const void* p) {
    uint32_t a;
    asm("{ .reg .u64 t; cvta.to.shared.u64 t, %1; cvt.u32.u64 %0, t; }"
        : "=r"(a) : "l"(p));
    return a;
}

__device__ __forceinline__ void cp16(uint32_t s, const void* g) {
    asm volatile("cp.async.cg.shared.global [%0], [%1], 16;" :: "r"(s), "l"(g));
}
#define CP_COMMIT asm volatile("cp.async.commit_group;" ::: "memory")
#define CP_WAIT0  asm volatile("cp.async.wait_group 0;" ::: "memory")
#define CP_WAIT1  asm volatile("cp.async.wait_group 1;" ::: "memory")

#define LDSM_X4(r0, r1, r2, r3, addr) \
    asm volatile("ldmatrix.sync.aligned.m8n8.x4.shared.b16 {%0,%1,%2,%3}, [%4];" \
                 : "=r"(r0), "=r"(r1), "=r"(r2), "=r"(r3) : "r"(addr))

#define LDSM_X2T(r0, r1, addr) \
    asm volatile("ldmatrix.sync.aligned.m8n8.x2.trans.shared.b16 {%0,%1}, [%2];" \
                 : "=r"(r0), "=r"(r1) : "r"(addr))

__device__ __forceinline__ void mma_bf(float c[4], const uint32_t a[4],
                                       uint32_t b0, uint32_t b1) {
    asm volatile(
        "mma.sync.aligned.m16n8k16.row.col.f32.bf16.bf16.f32 "
        "{%0,%1,%2,%3}, {%4,%5,%6,%7}, {%8,%9}, {%0,%1,%2,%3};"
        : "+f"(c[0]), "+f"(c[1]), "+f"(c[2]), "+f"(c[3])
        : "r"(a[0]), "r"(a[1]), "r"(a[2]), "r"(a[3]), "r"(b0), "r"(b1));
}

__device__ __forceinline__ void mma_hf(float c[4], const uint32_t a[4],
                                       uint32_t b0, uint32_t b1) {
    asm volatile(
        "mma.sync.aligned.m16n8k16.row.col.f32.f16.f16.f32 "
        "{%0,%1,%2,%3}, {%4,%5,%6,%7}, {%8,%9}, {%0,%1,%2,%3};"
        : "+f"(c[0]), "+f"(c[1]), "+f"(c[2]), "+f"(c[3])
        : "r"(a[0]), "r"(a[1]), "r"(a[2]), "r"(a[3]), "r"(b0), "r"(b1));
}

__device__ __forceinline__ uint32_t pack2(float x, float y) {
    __nv_bfloat162 t = __floats2bfloat162_rn(x, y);
    return *reinterpret_cast<uint32_t*>(&t);
}
__device__ __forceinline__ uint32_t pack2h(float x, float y) {
    __half2 t = __floats2half2_rn(x, y);
    return *reinterpret_cast<uint32_t*>(&t);
}

// ---------------------------------------------------------------------------
__global__ void split_kernel(const float* __restrict__ x,
                             bf16* __restrict__ hi, bf16* __restrict__ lo, int n)
{
    int i = blockIdx.x * blockDim.x + threadIdx.x;
    if (i < n) {
        float v = x[i];
        bf16 h = __float2bfloat16(v);
        hi[i] = h;
        lo[i] = __float2bfloat16(v - __bfloat162float(h));
    }
}

__global__ void norm_attn_kernel(float* __restrict__ attn,
                                 const float* __restrict__ lrow)
{
    long long row = blockIdx.x;
    float lv = lrow[row];
    float inv = (lv > 0.f) ? (1.f / lv) : 0.f;
    float4* p = (float4*)(attn + row * (long long)S_);
#pragma unroll
    for (int it = 0; it < 2; ++it) {
        int i = it * 256 + threadIdx.x;
        float4 v = p[i];
        v.x *= inv; v.y *= inv; v.z *= inv; v.w *= inv;
        p[i] = v;
    }
}

// ---------------------------------------------------------------------------
// Split-bf16 HMMA GEMM, 128x128 tile, 3-stage cp.async pipeline, ldmatrix.
// Outputs: f32 (Cf), bf16 hi/lo (Ch/Cl), or fp16 (Cq).
// ---------------------------------------------------------------------------
struct GemmArgs {
    const bf16 *Ahi, *Alo, *Wh, *Wl;
    const float* bias;
    float* Cf;
    bf16 *Ch, *Cl;
    half* Cq;
};
struct GemmArgs3 { GemmArgs a[3]; };

__global__ void __launch_bounds__(256, 2) gemm_mma_kernel(GemmArgs3 args)
{
    constexpr int PA = 40;
    constexpr int BUFE = 128 * PA;
    extern __shared__ __align__(16) bf16 gsm[];

    const GemmArgs ga = args.a[blockIdx.z];

    const int tid = threadIdx.x;
    const int w = tid >> 5, lane = tid & 31, gid = lane >> 2, tig = lane & 3;
    const int bm = blockIdx.y * 128, bn = blockIdx.x * 128;
    const int m0 = (w >> 1) * 32, n0 = (w & 1) * 64;

    const bf16* Asrc[3] = {ga.Ahi, ga.Alo, ga.Ahi};
    const bf16* Wsrc[3] = {ga.Wh,  ga.Wh,  ga.Wl};

    float c[2][8][4] = {};

    auto load_chunk = [&](int t, int buf) {
        int seg = t >> 5, kc = (t & 31) << 5;
        const bf16* As = Asrc[seg];
        const bf16* Ws = Wsrc[seg];
        bf16* sAb = gsm + buf * (2 * BUFE);
        bf16* sBb = sAb + BUFE;
#pragma unroll
        for (int i = 0; i < 2; ++i) {
            int idx = tid * 2 + i;
            int row = idx >> 2, q = idx & 3;
            cp16(smem_u32(&sAb[row * PA + q * 8]),
                 As + (size_t)(bm + row) * 1024 + kc + q * 8);
            cp16(smem_u32(&sBb[row * PA + q * 8]),
                 Ws + (size_t)(bn + row) * 1024 + kc + q * 8);
        }
    };

    load_chunk(0, 0); CP_COMMIT;
    load_chunk(1, 1); CP_COMMIT;

    for (int t = 0; t < 96; ++t) {
        if (t + 2 < 96) { CP_WAIT1; } else { CP_WAIT0; }
        __syncthreads();
        if (t + 2 < 96) { load_chunk(t + 2, (t + 2) % 3); CP_COMMIT; }

        const bf16* sAb = gsm + (t % 3) * (2 * BUFE);
        const bf16* sBb = sAb + BUFE;

#pragma unroll
        for (int ks = 0; ks < 32; ks += 16) {
            uint32_t a[2][4];
#pragma unroll
            for (int mi = 0; mi < 2; ++mi) {
                uint32_t ad = smem_u32(
                    &sAb[(m0 + mi * 16 + (lane & 15)) * PA + ks + ((lane >> 4) << 3)]);
                LDSM_X4(a[mi][0], a[mi][1], a[mi][2], a[mi][3], ad);
            }
#pragma unroll
            for (int p = 0; p < 4; ++p) {
                int nbase = n0 + p * 16;
                int br = nbase + (lane & 7) + ((lane >> 4) << 3);
                int bc = ks + (((lane >> 3) & 1) << 3);
                uint32_t b0, b1, b2, b3;
                LDSM_X4(b0, b1, b2, b3, smem_u32(&sBb[br * PA + bc]));
                mma_bf(c[0][2 * p],     a[0], b0, b1);
                mma_bf(c[1][2 * p],     a[1], b0, b1);
                mma_bf(c[0][2 * p + 1], a[0], b2, b3);
                mma_bf(c[1][2 * p + 1], a[1], b2, b3);
            }
        }
        __syncthreads();
    }

#pragma unroll
    for (int mi = 0; mi < 2; ++mi) {
#pragma unroll
        for (int ni = 0; ni < 8; ++ni) {
            int r0 = bm + m0 + mi * 16 + gid;
            int col = bn + n0 + ni * 8 + 2 * tig;
            float bv0 = ga.bias[col], bv1 = ga.bias[col + 1];
            float o00 = c[mi][ni][0] + bv0, o01 = c[mi][ni][1] + bv1;
            float o10 = c[mi][ni][2] + bv0, o11 = c[mi][ni][3] + bv1;
            if (ga.Cf) {
                *(float2*)&ga.Cf[(size_t)r0 * 1024 + col] = make_float2(o00, o01);
                *(float2*)&ga.Cf[(size_t)(r0 + 8) * 1024 + col] = make_float2(o10, o11);
            }
            if (ga.Cq) {
                *(uint32_t*)&ga.Cq[(size_t)r0 * 1024 + col]       = pack2h(o00, o01);
                *(uint32_t*)&ga.Cq[(size_t)(r0 + 8) * 1024 + col] = pack2h(o10, o11);
            }
            if (ga.Ch) {
                float h00 = __bfloat162float(__float2bfloat16(o00));
                float h01 = __bfloat162float(__float2bfloat16(o01));
                float h10 = __bfloat162float(__float2bfloat16(o10));
                float h11 = __bfloat162float(__float2bfloat16(o11));
                *(uint32_t*)&ga.Ch[(size_t)r0 * 1024 + col]       = pack2(o00, o01);
                *(uint32_t*)&ga.Ch[(size_t)(r0 + 8) * 1024 + col] = pack2(o10, o11);
                *(uint32_t*)&ga.Cl[(size_t)r0 * 1024 + col]       = pack2(o00 - h00, o01 - h01);
                *(uint32_t*)&ga.Cl[(size_t)(r0 + 8) * 1024 + col] = pack2(o10 - h10, o11 - h11);
            }
        }
    }
}

// ---------------------------------------------------------------------------
// One-pass fp16 flash attention:
//   S = Q@K^T (1-pass fp16 mma), p = exp(s/8) (no shift), write unnormalized
//   attn, l accumulated in registers, P kept in registers (C->A frag repack),
//   ctx += P@V (1-pass fp16), epilogue normalizes ctx and writes bf16 hi/lo.
//   Warp layout: 8 warps x 16 q-rows; each warp covers all 64 keys / 64 dk.
// ---------------------------------------------------------------------------
__global__ void __launch_bounds__(256) attn_fp16_kernel(
    const half* __restrict__ qf, const half* __restrict__ kf,
    const half* __restrict__ vf, const int* __restrict__ maskg,
    float* __restrict__ attn,
    bf16* __restrict__ ctxh, bf16* __restrict__ ctxl,
    float* __restrict__ lrow)
{
    constexpr int P = 72;
    constexpr int KVBUF = 2 * 64 * P;   // 9216 halves per stage (K + V)
    extern __shared__ __align__(16) half hsm[];
    half* Qs  = hsm;                     // 128*72
    half* KV0 = hsm + 9216;              // 2 stages
    int*  sMask = (int*)(hsm + 9216 + 2 * KVBUF);   // 2048 ints

    const int tid = threadIdx.x;
    const int w = tid >> 5, lane = tid & 31, gid = lane >> 2, tig = lane & 3;
    const int qt = blockIdx.x, h = blockIdx.y, b = blockIdx.z;
    const int q0 = qt * 128;
    const int m0 = w * 16;

    // ---- Q + full mask row (group 0) ----
    {
        size_t base = (size_t)(b * S_ + q0) * D_ + h * 64;
#pragma unroll
        for (int i = 0; i < 4; ++i) {
            int idx = tid * 4 + i;       // 0..1023
            int row = idx >> 3, qq = idx & 7;
            cp16(smem_u32(&Qs[row * P + qq * 8]), qf + base + (size_t)row * D_ + qq * 8);
        }
#pragma unroll
        for (int i = 0; i < 2; ++i) {
            int j = tid * 2 + i;         // 0..511
            cp16(smem_u32(&sMask[j * 4]), maskg + b * S_ + j * 4);
        }
        CP_COMMIT;
    }

    auto load_kv = [&](int kt, int buf) {
        size_t kbase = (size_t)(b * S_ + kt * 64) * D_ + h * 64;
        half* Ks_ = KV0 + buf * KVBUF;
        half* Vs_ = Ks_ + 64 * P;
#pragma unroll
        for (int i = 0; i < 2; ++i) {
            int idx = tid * 2 + i;       // 0..511
            int row = idx >> 3, qq = idx & 7;
            size_t go = kbase + (size_t)row * D_ + qq * 8;
            cp16(smem_u32(&Ks_[row * P + qq * 8]), kf + go);
            cp16(smem_u32(&Vs_[row * P + qq * 8]), vf + go);
        }
    };

    load_kv(0, 0); CP_COMMIT;

    float ctxc[8][4] = {};
    float lacc0 = 0.f, lacc1 = 0.f;

    for (int kt = 0; kt < 32; ++kt) {
        const int kb = kt * 64;
        const int buf = kt & 1;
        if (kt + 1 < 32) { load_kv(kt + 1, buf ^ 1); CP_COMMIT; CP_WAIT1; }
        else             { CP_WAIT0; }
        __syncthreads();

        const half* Ks_ = KV0 + buf * KVBUF;
        const half* Vs_ = Ks_ + 64 * P;

        // ---- S = Q @ K^T (single fp16 pass) ----
        float sc[8][4] = {};
#pragma unroll
        for (int ks = 0; ks < 64; ks += 16) {
            uint32_t a[4];
            LDSM_X4(a[0], a[1], a[2], a[3],
                    smem_u32(&Qs[(m0 + (lane & 15)) * P + ks + ((lane >> 4) << 3)]));
#pragma unroll
            for (int p = 0; p < 4; ++p) {
                int br = p * 16 + (lane & 7) + ((lane >> 4) << 3);
                int bc = ks + (((lane >> 3) & 1) << 3);
                uint32_t b0, b1, b2, b3;
                LDSM_X4(b0, b1, b2, b3, smem_u32(&Ks_[br * P + bc]));
                mma_hf(sc[2 * p],     a, b0, b1);
                mma_hf(sc[2 * p + 1], a, b2, b3);
            }
        }

        // ---- exp (no shift), attn write, l accum, repack P to fp16 A-frags ----
        const int* mk = sMask + kt * 64;
        uint32_t ah[4][4];
#pragma unroll
        for (int ni = 0; ni < 8; ++ni) {
            int cc = ni * 8 + 2 * tig;
            bool k0 = mk[cc] != 0, k1 = mk[cc + 1] != 0;
            float p00 = k0 ? __expf(sc[ni][0] * 0.125f) : 0.f;
            float p01 = k1 ? __expf(sc[ni][1] * 0.125f) : 0.f;
            float p10 = k0 ? __expf(sc[ni][2] * 0.125f) : 0.f;
            float p11 = k1 ? __expf(sc[ni][3] * 0.125f) : 0.f;
            lacc0 += p00 + p01;
            lacc1 += p10 + p11;
            if (attn) {
                size_t arow = ((size_t)((b * H_ + h) * S_) + q0 + m0 + gid) * S_ + kb + cc;
                *(float2*)&attn[arow]                  = make_float2(p00, p01);
                *(float2*)&attn[arow + 8 * (size_t)S_] = make_float2(p10, p11);
            }
            int t = ni >> 1, bse = (ni & 1) * 2;
            ah[t][bse]     = pack2h(p00, p01);
            ah[t][bse + 1] = pack2h(p10, p11);
        }

        // ---- ctx += P @ V (single fp16 pass) ----
#pragma unroll
        for (int t = 0; t < 4; ++t) {
#pragma unroll
            for (int ni = 0; ni < 8; ++ni) {
                uint32_t b0, b1;
                LDSM_X2T(b0, b1,
                         smem_u32(&Vs_[(t * 16 + (lane & 15)) * P + ni * 8]));
                mma_hf(ctxc[ni], ah[t], b0, b1);
            }
        }
        __syncthreads();
    }

    // ---- l: lane-group reduce (each warp owns exclusive rows) ----
    lacc0 += __shfl_xor_sync(0xffffffffu, lacc0, 1);
    lacc0 += __shfl_xor_sync(0xffffffffu, lacc0, 2);
    lacc1 += __shfl_xor_sync(0xffffffffu, lacc1, 1);
    lacc1 += __shfl_xor_sync(0xffffffffu, lacc1, 2);
    const float invl0 = (lacc0 > 0.f) ? (1.f / lacc0) : 0.f;
    const float invl1 = (lacc1 > 0.f) ? (1.f / lacc1) : 0.f;
    if (tig == 0) {
        lrow[(size_t)(b * H_ + h) * S_ + q0 + m0 + gid]     = lacc0;
        lrow[(size_t)(b * H_ + h) * S_ + q0 + m0 + gid + 8] = lacc1;
    }

    // ---- ctx write (normalized, bf16 hi/lo) ----
#pragma unroll
    for (int ni = 0; ni < 8; ++ni) {
        int r = q0 + m0 + gid;
        int col = h * 64 + ni * 8 + 2 * tig;
        size_t base = ((size_t)(b * S_) + r) * D_ + col;
        float o00 = ctxc[ni][0] * invl0, o01 = ctxc[ni][1] * invl0;
        float o10 = ctxc[ni][2] * invl1, o11 = ctxc[ni][3] * invl1;
        float h00 = __bfloat162float(__float2bfloat16(o00));
        float h01 = __bfloat162float(__float2bfloat16(o01));
        float h10 = __bfloat162float(__float2bfloat16(o10));
        float h11 = __bfloat162float(__float2bfloat16(o11));
        *(uint32_t*)&ctxh[base]                  = pack2(o00, o01);
        *(uint32_t*)&ctxh[base + 8 * (size_t)D_] = pack2(o10, o11);
        *(uint32_t*)&ctxl[base]                  = pack2(o00 - h00, o01 - h01);
        *(uint32_t*)&ctxl[base + 8 * (size_t)D_] = pack2(o10 - h10, o11 - h11);
    }
}

// ---------------------------------------------------------------------------
extern "C" void kernel_launch(void* const* d_in, const int* in_sizes, int n_in,
                              void* d_out, int out_size)
{
    const float* hs   = (const float*)d_in[0];
    const int*   mask = (const int*)  d_in[1];
    const float* Wq   = (const float*)d_in[2];
    const float* bq   = (const float*)d_in[3];
    const float* Wk   = (const float*)d_in[4];
    const float* bk   = (const float*)d_in[5];
    const float* Wv   = (const float*)d_in[6];
    const float* bv   = (const float*)d_in[7];
    const float* Wo   = (const float*)d_in[8];
    const float* bo   = (const float*)d_in[9];

    float* outp = (float*)d_out;

    bf16 *ahi, *alo, *chp, *clp;
    half *qfp, *kfp, *vfp;
    bf16 *wqh, *wql, *wkh, *wkl, *wvh, *wvl, *woh, *wol;
    float* lp;
    cudaGetSymbolAddress((void**)&ahi,  g_ahi);
    cudaGetSymbolAddress((void**)&alo,  g_alo);
    cudaGetSymbolAddress((void**)&qfp,  g_qf);
    cudaGetSymbolAddress((void**)&kfp,  g_kf);
    cudaGetSymbolAddress((void**)&vfp,  g_vf);
    cudaGetSymbolAddress((void**)&chp,  g_ch);
    cudaGetSymbolAddress((void**)&clp,  g_cl);
    cudaGetSymbolAddress((void**)&wqh,  g_wqh);
    cudaGetSymbolAddress((void**)&wql,  g_wql);
    cudaGetSymbolAddress((void**)&wkh,  g_wkh);
    cudaGetSymbolAddress((void**)&wkl,  g_wkl);
    cudaGetSymbolAddress((void**)&wvh,  g_wvh);
    cudaGetSymbolAddress((void**)&wvl,  g_wvl);
    cudaGetSymbolAddress((void**)&woh,  g_woh);
    cudaGetSymbolAddress((void**)&wol,  g_wol);
    cudaGetSymbolAddress((void**)&lp,   g_lrow);

    float* attnp = nullptr;
    if ((long long)out_size >= OUT_ELEMS + ATTN_ELEMS)
        attnp = outp + OUT_ELEMS;

    // 1. splits
    split_kernel<<<(M_ * D_ + 255) / 256, 256>>>(hs, ahi, alo, M_ * D_);
    split_kernel<<<(D_ * D_ + 255) / 256, 256>>>(Wq, wqh, wql, D_ * D_);
    split_kernel<<<(D_ * D_ + 255) / 256, 256>>>(Wk, wkh, wkl, D_ * D_);
    split_kernel<<<(D_ * D_ + 255) / 256, 256>>>(Wv, wvh, wvl, D_ * D_);
    split_kernel<<<(D_ * D_ + 255) / 256, 256>>>(Wo, woh, wol, D_ * D_);

    const int gemm_smem = 3 * 2 * 128 * 40 * (int)sizeof(bf16);   // 61440
    cudaFuncSetAttribute(gemm_mma_kernel,
                         cudaFuncAttributeMaxDynamicSharedMemorySize, gemm_smem);

    // 2. fused Q/K/V projections (fp16 outputs)
    {
        GemmArgs3 a3;
        a3.a[0] = {ahi, alo, wqh, wql, bq, nullptr, nullptr, nullptr, qfp};
        a3.a[1] = {ahi, alo, wkh, wkl, bk, nullptr, nullptr, nullptr, kfp};
        a3.a[2] = {ahi, alo, wvh, wvl, bv, nullptr, nullptr, nullptr, vfp};
        dim3 gg(D_ / 128, M_ / 128, 3);
        gemm_mma_kernel<<<gg, 256, gemm_smem>>>(a3);
    }

    // 3. one-pass fp16 attention (unnormalized attn; normalized ctx)
    {
        dim3 ga(S_ / 128, H_, B_);
        int smA = (9216 + 2 * 9216) * (int)sizeof(half) + 2048 * (int)sizeof(int);
        cudaFuncSetAttribute(attn_fp16_kernel,
                             cudaFuncAttributeMaxDynamicSharedMemorySize, smA);
        attn_fp16_kernel<<<ga, 256, smA>>>(qfp, kfp, vfp, mask, attnp,
                                           chp, clp, lp);
    }

    // 4. normalize attn rows
    if (attnp)
        norm_attn_kernel<<<B_ * H_ * S_, 256>>>(attnp, lp);

    // 5. output projection (f32 out + bias)
    {
        GemmArgs3 a3;
        a3.a[0] = {chp, clp, woh, wol, bo, outp, nullptr, nullptr, nullptr};
        dim3 gg(D_ / 128, M_ / 128, 1);
        gemm_mma_kernel<<<gg, 256, gemm_smem>>>(a3);
    }
}

// round 7
// speedup vs baseline: 2.1266x; 1.4950x over previous
#include <cuda_runtime.h>
#include <cuda_bf16.h>
#include <cuda_fp16.h>
#include <cstdint>

namespace {
constexpr int B_  = 4;
constexpr int S_  = 2048;
constexpr int D_  = 1024;
constexpr int H_  = 16;
constexpr int M_  = B_ * S_;  // 8192
constexpr long long OUT_ELEMS  = (long long)M_ * D_;
constexpr long long ATTN_ELEMS = (long long)B_ * H_ * S_ * S_;
}

// ------------------------- device scratch (no allocs) -----------------------
__device__ half g_ahi[M_ * D_], g_alo[M_ * D_];
__device__ half g_qf[M_ * D_], g_kf[M_ * D_], g_vf[M_ * D_];
__device__ half g_ch[M_ * D_], g_cl[M_ * D_];
__device__ half g_wq[D_ * D_], g_wk[D_ * D_], g_wv[D_ * D_], g_wo[D_ * D_];

// ----------------------------- helpers --------------------------------------
__device__ __forceinline__ uint32_t smem_u32(const void* p) {
    uint32_t a;
    asm("{ .reg .u64 t; cvta.to.shared.u64 t, %1; cvt.u32.u64 %0, t; }"
        : "=r"(a) : "l"(p));
    return a;
}

__device__ __forceinline__ void cp16(uint32_t s, const void* g) {
    asm volatile("cp.async.cg.shared.global [%0], [%1], 16;" :: "r"(s), "l"(g));
}
#define CP_COMMIT asm volatile("cp.async.commit_group;" ::: "memory")
#define CP_WAIT0  asm volatile("cp.async.wait_group 0;" ::: "memory")
#define CP_WAIT1  asm volatile("cp.async.wait_group 1;" ::: "memory")

#define LDSM_X4(r0, r1, r2, r3, addr) \
    asm volatile("ldmatrix.sync.aligned.m8n8.x4.shared.b16 {%0,%1,%2,%3}, [%4];" \
                 : "=r"(r0), "=r"(r1), "=r"(r2), "=r"(r3) : "r"(addr))

#define LDSM_X2T(r0, r1, addr) \
    asm volatile("ldmatrix.sync.aligned.m8n8.x2.trans.shared.b16 {%0,%1}, [%2];" \
                 : "=r"(r0), "=r"(r1) : "r"(addr))

__device__ __forceinline__ void mma_hf(float c[4], const uint32_t a[4],
                                       uint32_t b0, uint32_t b1) {
    asm volatile(
        "mma.sync.aligned.m16n8k16.row.col.f32.f16.f16.f32 "
        "{%0,%1,%2,%3}, {%4,%5,%6,%7}, {%8,%9}, {%0,%1,%2,%3};"
        : "+f"(c[0]), "+f"(c[1]), "+f"(c[2]), "+f"(c[3])
        : "r"(a[0]), "r"(a[1]), "r"(a[2]), "r"(a[3]), "r"(b0), "r"(b1));
}

__device__ __forceinline__ uint32_t pack2h(float x, float y) {
    __half2 t = __floats2half2_rn(x, y);
    return *reinterpret_cast<uint32_t*>(&t);
}

// ---------------------------------------------------------------------------
__global__ void split_h_kernel(const float* __restrict__ x,
                               half* __restrict__ hi, half* __restrict__ lo, int n)
{
    int i = blockIdx.x * blockDim.x + threadIdx.x;
    if (i < n) {
        float v = x[i];
        half h = __float2half_rn(v);
        hi[i] = h;
        lo[i] = __float2half_rn(v - __half2float(h));
    }
}

__global__ void cast_h_kernel(const float* __restrict__ x,
                              half* __restrict__ hi, int n)
{
    int i = blockIdx.x * blockDim.x + threadIdx.x;
    if (i < n) hi[i] = __float2half_rn(x[i]);
}

// ---------------------------------------------------------------------------
// 2-pass fp16-split HMMA GEMM: C = (Ahi + Alo) @ Wh^T + bias
// 128x128 tile, K-chunk 32, 3-stage cp.async pipeline; W tile shared by both
// passes (loaded once per chunk).
// ---------------------------------------------------------------------------
struct GemmArgs {
    const half *Ahi, *Alo, *Wh;
    const float* bias;
    float* Cf;
    half* Cq;
};
struct GemmArgs3 { GemmArgs a[3]; };

__global__ void __launch_bounds__(256, 2) gemm_mma_kernel(GemmArgs3 args)
{
    constexpr int PA = 40;
    constexpr int BUFE = 128 * PA;        // 5120 halves per sub-tile
    constexpr int STAGE = 3 * BUFE;       // Ahi, Alo, W
    extern __shared__ __align__(16) half gsm[];

    const GemmArgs ga = args.a[blockIdx.z];

    const int tid = threadIdx.x;
    const int w = tid >> 5, lane = tid & 31, gid = lane >> 2, tig = lane & 3;
    const int bm = blockIdx.y * 128, bn = blockIdx.x * 128;
    const int m0 = (w >> 1) * 32, n0 = (w & 1) * 64;

    float c[2][8][4] = {};

    auto load_chunk = [&](int t, int buf) {
        int kc = t << 5;
        half* sAh = gsm + buf * STAGE;
        half* sAl = sAh + BUFE;
        half* sW  = sAh + 2 * BUFE;
#pragma unroll
        for (int i = 0; i < 2; ++i) {
            int idx = tid * 2 + i;           // 0..511
            int row = idx >> 2, q = idx & 3;
            size_t go = (size_t)row * 1024 + kc + q * 8;
            cp16(smem_u32(&sAh[row * PA + q * 8]), ga.Ahi + (size_t)bm * 1024 + go);
            cp16(smem_u32(&sAl[row * PA + q * 8]), ga.Alo + (size_t)bm * 1024 + go);
            cp16(smem_u32(&sW[row * PA + q * 8]),  ga.Wh  + (size_t)bn * 1024 + go);
        }
    };

    load_chunk(0, 0); CP_COMMIT;
    load_chunk(1, 1); CP_COMMIT;

    for (int t = 0; t < 32; ++t) {
        if (t + 2 < 32) { CP_WAIT1; } else { CP_WAIT0; }
        __syncthreads();
        if (t + 2 < 32) { load_chunk(t + 2, (t + 2) % 3); CP_COMMIT; }

        const half* sAh = gsm + (t % 3) * STAGE;
        const half* sAl = sAh + BUFE;
        const half* sW  = sAh + 2 * BUFE;

#pragma unroll
        for (int ks = 0; ks < 32; ks += 16) {
            uint32_t ah[2][4], al[2][4];
#pragma unroll
            for (int mi = 0; mi < 2; ++mi) {
                int ro = (m0 + mi * 16 + (lane & 15)) * PA + ks + ((lane >> 4) << 3);
                LDSM_X4(ah[mi][0], ah[mi][1], ah[mi][2], ah[mi][3], smem_u32(&sAh[ro]));
                LDSM_X4(al[mi][0], al[mi][1], al[mi][2], al[mi][3], smem_u32(&sAl[ro]));
            }
#pragma unroll
            for (int p = 0; p < 4; ++p) {
                int br = n0 + p * 16 + (lane & 7) + ((lane >> 4) << 3);
                int bc = ks + (((lane >> 3) & 1) << 3);
                uint32_t b0, b1, b2, b3;
                LDSM_X4(b0, b1, b2, b3, smem_u32(&sW[br * PA + bc]));
                mma_hf(c[0][2 * p],     ah[0], b0, b1);
                mma_hf(c[1][2 * p],     ah[1], b0, b1);
                mma_hf(c[0][2 * p],     al[0], b0, b1);
                mma_hf(c[1][2 * p],     al[1], b0, b1);
                mma_hf(c[0][2 * p + 1], ah[0], b2, b3);
                mma_hf(c[1][2 * p + 1], ah[1], b2, b3);
                mma_hf(c[0][2 * p + 1], al[0], b2, b3);
                mma_hf(c[1][2 * p + 1], al[1], b2, b3);
            }
        }
        __syncthreads();
    }

#pragma unroll
    for (int mi = 0; mi < 2; ++mi) {
#pragma unroll
        for (int ni = 0; ni < 8; ++ni) {
            int r0 = bm + m0 + mi * 16 + gid;
            int col = bn + n0 + ni * 8 + 2 * tig;
            float bv0 = ga.bias[col], bv1 = ga.bias[col + 1];
            float o00 = c[mi][ni][0] + bv0, o01 = c[mi][ni][1] + bv1;
            float o10 = c[mi][ni][2] + bv0, o11 = c[mi][ni][3] + bv1;
            if (ga.Cf) {
                *(float2*)&ga.Cf[(size_t)r0 * 1024 + col] = make_float2(o00, o01);
                *(float2*)&ga.Cf[(size_t)(r0 + 8) * 1024 + col] = make_float2(o10, o11);
            }
            if (ga.Cq) {
                *(uint32_t*)&ga.Cq[(size_t)r0 * 1024 + col]       = pack2h(o00, o01);
                *(uint32_t*)&ga.Cq[(size_t)(r0 + 8) * 1024 + col] = pack2h(o10, o11);
            }
        }
    }
}

// ---------------------------------------------------------------------------
// Two-phase fp16 flash attention:
//   Phase 1: S = Q@K^T (fp16 mma), l[row] = sum exp(s/8)   (K only)
//   Phase 2: recompute S, p = exp(s/8)/l -> write NORMALIZED attn,
//            ctx += p @ V (P register-resident), ctx out as fp16 hi/lo.
//   Warp layout: 8 warps x 16 q-rows; each warp covers all 64 keys / 64 dk.
// ---------------------------------------------------------------------------
__global__ void __launch_bounds__(256) attn_fp16_kernel(
    const half* __restrict__ qf, const half* __restrict__ kf,
    const half* __restrict__ vf, const int* __restrict__ maskg,
    float* __restrict__ attn,
    half* __restrict__ ctxh, half* __restrict__ ctxl)
{
    constexpr int P = 72;
    constexpr int KTILE = 64 * P;        // 4608 halves
    extern __shared__ __align__(16) half hsm[];
    half* Qs = hsm;                      // 128*72 = 9216
    half* K0 = hsm + 9216;               // 2 K stages
    half* V0 = hsm + 9216 + 2 * KTILE;   // 2 V stages
    int*  sMask = (int*)(hsm + 9216 + 4 * KTILE);   // 2048 ints

    const int tid = threadIdx.x;
    const int w = tid >> 5, lane = tid & 31, gid = lane >> 2, tig = lane & 3;
    const int qt = blockIdx.x, h = blockIdx.y, b = blockIdx.z;
    const int q0 = qt * 128;
    const int m0 = w * 16;

    // ---- Q + full mask row ----
    {
        size_t base = (size_t)(b * S_ + q0) * D_ + h * 64;
#pragma unroll
        for (int i = 0; i < 4; ++i) {
            int idx = tid * 4 + i;
            int row = idx >> 3, qq = idx & 7;
            cp16(smem_u32(&Qs[row * P + qq * 8]), qf + base + (size_t)row * D_ + qq * 8);
        }
#pragma unroll
        for (int i = 0; i < 2; ++i) {
            int j = tid * 2 + i;
            cp16(smem_u32(&sMask[j * 4]), maskg + b * S_ + j * 4);
        }
        CP_COMMIT;
    }

    auto load_k = [&](int kt, int buf) {
        size_t kbase = (size_t)(b * S_ + kt * 64) * D_ + h * 64;
        half* Ks_ = K0 + buf * KTILE;
#pragma unroll
        for (int i = 0; i < 2; ++i) {
            int idx = tid * 2 + i;
            int row = idx >> 3, qq = idx & 7;
            cp16(smem_u32(&Ks_[row * P + qq * 8]), kf + kbase + (size_t)row * D_ + qq * 8);
        }
    };
    auto load_kv = [&](int kt, int buf) {
        size_t kbase = (size_t)(b * S_ + kt * 64) * D_ + h * 64;
        half* Ks_ = K0 + buf * KTILE;
        half* Vs_ = V0 + buf * KTILE;
#pragma unroll
        for (int i = 0; i < 2; ++i) {
            int idx = tid * 2 + i;
            int row = idx >> 3, qq = idx & 7;
            size_t go = kbase + (size_t)row * D_ + qq * 8;
            cp16(smem_u32(&Ks_[row * P + qq * 8]), kf + go);
            cp16(smem_u32(&Vs_[row * P + qq * 8]), vf + go);
        }
    };

    // S = Q@K^T for this warp's 16 rows x 64 keys (single fp16 pass)
    auto computeS = [&](const half* Ks_, float sc[8][4]) {
#pragma unroll
        for (int ks = 0; ks < 64; ks += 16) {
            uint32_t a[4];
            LDSM_X4(a[0], a[1], a[2], a[3],
                    smem_u32(&Qs[(m0 + (lane & 15)) * P + ks + ((lane >> 4) << 3)]));
#pragma unroll
            for (int p = 0; p < 4; ++p) {
                int br = p * 16 + (lane & 7) + ((lane >> 4) << 3);
                int bc = ks + (((lane >> 3) & 1) << 3);
                uint32_t b0, b1, b2, b3;
                LDSM_X4(b0, b1, b2, b3, smem_u32(&Ks_[br * P + bc]));
                mma_hf(sc[2 * p],     a, b0, b1);
                mma_hf(sc[2 * p + 1], a, b2, b3);
            }
        }
    };

    // ================= phase 1: l =================
    load_k(0, 0); CP_COMMIT;
    float lacc0 = 0.f, lacc1 = 0.f;

    for (int kt = 0; kt < 32; ++kt) {
        const int buf = kt & 1;
        if (kt + 1 < 32) { load_k(kt + 1, buf ^ 1); CP_COMMIT; CP_WAIT1; }
        else             { CP_WAIT0; }
        __syncthreads();

        float sc[8][4] = {};
        computeS(K0 + buf * KTILE, sc);

        const int* mk = sMask + kt * 64;
#pragma unroll
        for (int ni = 0; ni < 8; ++ni) {
            int cc = ni * 8 + 2 * tig;
            bool k0 = mk[cc] != 0, k1 = mk[cc + 1] != 0;
            lacc0 += (k0 ? __expf(sc[ni][0] * 0.125f) : 0.f)
                   + (k1 ? __expf(sc[ni][1] * 0.125f) : 0.f);
            lacc1 += (k0 ? __expf(sc[ni][2] * 0.125f) : 0.f)
                   + (k1 ? __expf(sc[ni][3] * 0.125f) : 0.f);
        }
        __syncthreads();
    }

    lacc0 += __shfl_xor_sync(0xffffffffu, lacc0, 1);
    lacc0 += __shfl_xor_sync(0xffffffffu, lacc0, 2);
    lacc1 += __shfl_xor_sync(0xffffffffu, lacc1, 1);
    lacc1 += __shfl_xor_sync(0xffffffffu, lacc1, 2);
    const float invl0 = (lacc0 > 0.f) ? (1.f / lacc0) : 0.f;
    const float invl1 = (lacc1 > 0.f) ? (1.f / lacc1) : 0.f;

    // ================= phase 2: attn + ctx =================
    load_kv(0, 0); CP_COMMIT;

    float ctxc[8][4] = {};

    for (int kt = 0; kt < 32; ++kt) {
        const int kb = kt * 64;
        const int buf = kt & 1;
        if (kt + 1 < 32) { load_kv(kt + 1, buf ^ 1); CP_COMMIT; CP_WAIT1; }
        else             { CP_WAIT0; }
        __syncthreads();

        const half* Ks_ = K0 + buf * KTILE;
        const half* Vs_ = V0 + buf * KTILE;

        float sc[8][4] = {};
        computeS(Ks_, sc);

        const int* mk = sMask + kt * 64;
        uint32_t ah[4][4];
#pragma unroll
        for (int ni = 0; ni < 8; ++ni) {
            int cc = ni * 8 + 2 * tig;
            bool k0 = mk[cc] != 0, k1 = mk[cc + 1] != 0;
            float p00 = k0 ? (__expf(sc[ni][0] * 0.125f) * invl0) : 0.f;
            float p01 = k1 ? (__expf(sc[ni][1] * 0.125f) * invl0) : 0.f;
            float p10 = k0 ? (__expf(sc[ni][2] * 0.125f) * invl1) : 0.f;
            float p11 = k1 ? (__expf(sc[ni][3] * 0.125f) * invl1) : 0.f;
            if (attn) {
                size_t arow = ((size_t)((b * H_ + h) * S_) + q0 + m0 + gid) * S_ + kb + cc;
                *(float2*)&attn[arow]                  = make_float2(p00, p01);
                *(float2*)&attn[arow + 8 * (size_t)S_] = make_float2(p10, p11);
            }
            int t = ni >> 1, bse = (ni & 1) * 2;
            ah[t][bse]     = pack2h(p00, p01);
            ah[t][bse + 1] = pack2h(p10, p11);
        }

#pragma unroll
        for (int t = 0; t < 4; ++t) {
#pragma unroll
            for (int ni = 0; ni < 8; ++ni) {
                uint32_t b0, b1;
                LDSM_X2T(b0, b1,
                         smem_u32(&Vs_[(t * 16 + (lane & 15)) * P + ni * 8]));
                mma_hf(ctxc[ni], ah[t], b0, b1);
            }
        }
        __syncthreads();
    }

    // ---- ctx write (already normalized; fp16 hi/lo) ----
#pragma unroll
    for (int ni = 0; ni < 8; ++ni) {
        int r = q0 + m0 + gid;
        int col = h * 64 + ni * 8 + 2 * tig;
        size_t base = ((size_t)(b * S_) + r) * D_ + col;
        float o00 = ctxc[ni][0], o01 = ctxc[ni][1];
        float o10 = ctxc[ni][2], o11 = ctxc[ni][3];
        float h00 = __half2float(__float2half_rn(o00));
        float h01 = __half2float(__float2half_rn(o01));
        float h10 = __half2float(__float2half_rn(o10));
        float h11 = __half2float(__float2half_rn(o11));
        *(uint32_t*)&ctxh[base]                  = pack2h(o00, o01);
        *(uint32_t*)&ctxh[base + 8 * (size_t)D_] = pack2h(o10, o11);
        *(uint32_t*)&ctxl[base]                  = pack2h(o00 - h00, o01 - h01);
        *(uint32_t*)&ctxl[base + 8 * (size_t)D_] = pack2h(o10 - h10, o11 - h11);
    }
}

// ---------------------------------------------------------------------------
extern "C" void kernel_launch(void* const* d_in, const int* in_sizes, int n_in,
                              void* d_out, int out_size)
{
    const float* hs   = (const float*)d_in[0];
    const int*   mask = (const int*)  d_in[1];
    const float* Wq   = (const float*)d_in[2];
    const float* bq   = (const float*)d_in[3];
    const float* Wk   = (const float*)d_in[4];
    const float* bk   = (const float*)d_in[5];
    const float* Wv   = (const float*)d_in[6];
    const float* bv   = (const float*)d_in[7];
    const float* Wo   = (const float*)d_in[8];
    const float* bo   = (const float*)d_in[9];

    float* outp = (float*)d_out;

    half *ahi, *alo, *qfp, *kfp, *vfp, *chp, *clp, *wqp, *wkp, *wvp, *wop;
    cudaGetSymbolAddress((void**)&ahi, g_ahi);
    cudaGetSymbolAddress((void**)&alo, g_alo);
    cudaGetSymbolAddress((void**)&qfp, g_qf);
    cudaGetSymbolAddress((void**)&kfp, g_kf);
    cudaGetSymbolAddress((void**)&vfp, g_vf);
    cudaGetSymbolAddress((void**)&chp, g_ch);
    cudaGetSymbolAddress((void**)&clp, g_cl);
    cudaGetSymbolAddress((void**)&wqp, g_wq);
    cudaGetSymbolAddress((void**)&wkp, g_wk);
    cudaGetSymbolAddress((void**)&wvp, g_wv);
    cudaGetSymbolAddress((void**)&wop, g_wo);

    float* attnp = nullptr;
    if ((long long)out_size >= OUT_ELEMS + ATTN_ELEMS)
        attnp = outp + OUT_ELEMS;

    // 1. splits / casts to fp16
    split_h_kernel<<<(M_ * D_ + 255) / 256, 256>>>(hs, ahi, alo, M_ * D_);
    cast_h_kernel<<<(D_ * D_ + 255) / 256, 256>>>(Wq, wqp, D_ * D_);
    cast_h_kernel<<<(D_ * D_ + 255) / 256, 256>>>(Wk, wkp, D_ * D_);
    cast_h_kernel<<<(D_ * D_ + 255) / 256, 256>>>(Wv, wvp, D_ * D_);
    cast_h_kernel<<<(D_ * D_ + 255) / 256, 256>>>(Wo, wop, D_ * D_);

    const int gemm_smem = 3 * 3 * 128 * 40 * (int)sizeof(half);   // 92160
    cudaFuncSetAttribute(gemm_mma_kernel,
                         cudaFuncAttributeMaxDynamicSharedMemorySize, gemm_smem);

    // 2. fused Q/K/V projections (fp16 outputs)
    {
        GemmArgs3 a3;
        a3.a[0] = {ahi, alo, wqp, bq, nullptr, qfp};
        a3.a[1] = {ahi, alo, wkp, bk, nullptr, kfp};
        a3.a[2] = {ahi, alo, wvp, bv, nullptr, vfp};
        dim3 gg(D_ / 128, M_ / 128, 3);
        gemm_mma_kernel<<<gg, 256, gemm_smem>>>(a3);
    }

    // 3. two-phase fp16 attention (normalized attn; fp16 hi/lo ctx)
    {
        dim3 ga(S_ / 128, H_, B_);
        int smA = (9216 + 4 * 4608) * (int)sizeof(half) + 2048 * (int)sizeof(int);
        cudaFuncSetAttribute(attn_fp16_kernel,
                             cudaFuncAttributeMaxDynamicSharedMemorySize, smA);
        attn_fp16_kernel<<<ga, 256, smA>>>(qfp, kfp, vfp, mask, attnp, chp, clp);
    }

    // 4. output projection (f32 out + bias)
    {
        GemmArgs3 a3;
        a3.a[0] = {chp, clp, wop, bo, outp, nullptr};
        dim3 gg(D_ / 128, M_ / 128, 1);
        gemm_mma_kernel<<<gg, 256, gemm_smem>>>(a3);
    }
}

// round 8
// speedup vs baseline: 2.1711x; 1.0209x over previous
#include <cuda_runtime.h>
#include <cuda_fp16.h>
#include <cstdint>

namespace {
constexpr int B_  = 4;
constexpr int S_  = 2048;
constexpr int D_  = 1024;
constexpr int H_  = 16;
constexpr int M_  = B_ * S_;  // 8192
constexpr long long OUT_ELEMS  = (long long)M_ * D_;
constexpr long long ATTN_ELEMS = (long long)B_ * H_ * S_ * S_;
}

// ------------------------- device scratch (no allocs) -----------------------
__device__ half g_ah[M_ * D_];
__device__ half g_qf[M_ * D_], g_kf[M_ * D_], g_vf[M_ * D_];
__device__ half g_ch[M_ * D_], g_cl[M_ * D_];
__device__ half g_wq[D_ * D_], g_wk[D_ * D_], g_wv[D_ * D_], g_wo[D_ * D_];

// ----------------------------- helpers --------------------------------------
__device__ __forceinline__ uint32_t smem_u32(const void* p) {
    uint32_t a;
    asm("{ .reg .u64 t; cvta.to.shared.u64 t, %1; cvt.u32.u64 %0, t; }"
        : "=r"(a) : "l"(p));
    return a;
}

__device__ __forceinline__ void cp16(uint32_t s, const void* g) {
    asm volatile("cp.async.cg.shared.global [%0], [%1], 16;" :: "r"(s), "l"(g));
}
#define CP_COMMIT asm volatile("cp.async.commit_group;" ::: "memory")
#define CP_WAIT0  asm volatile("cp.async.wait_group 0;" ::: "memory")
#define CP_WAIT1  asm volatile("cp.async.wait_group 1;" ::: "memory")

#define LDSM_X4(r0, r1, r2, r3, addr) \
    asm volatile("ldmatrix.sync.aligned.m8n8.x4.shared.b16 {%0,%1,%2,%3}, [%4];" \
                 : "=r"(r0), "=r"(r1), "=r"(r2), "=r"(r3) : "r"(addr))

#define LDSM_X2T(r0, r1, addr) \
    asm volatile("ldmatrix.sync.aligned.m8n8.x2.trans.shared.b16 {%0,%1}, [%2];" \
                 : "=r"(r0), "=r"(r1) : "r"(addr))

__device__ __forceinline__ void mma_hf(float c[4], const uint32_t a[4],
                                       uint32_t b0, uint32_t b1) {
    asm volatile(
        "mma.sync.aligned.m16n8k16.row.col.f32.f16.f16.f32 "
        "{%0,%1,%2,%3}, {%4,%5,%6,%7}, {%8,%9}, {%0,%1,%2,%3};"
        : "+f"(c[0]), "+f"(c[1]), "+f"(c[2]), "+f"(c[3])
        : "r"(a[0]), "r"(a[1]), "r"(a[2]), "r"(a[3]), "r"(b0), "r"(b1));
}

__device__ __forceinline__ uint32_t pack2h(float x, float y) {
    __half2 t = __floats2half2_rn(x, y);
    return *reinterpret_cast<uint32_t*>(&t);
}

// ---------------------------------------------------------------------------
__global__ void cast_h_kernel(const float* __restrict__ x,
                              half* __restrict__ hi, int n)
{
    int i = blockIdx.x * blockDim.x + threadIdx.x;
    if (i < n) hi[i] = __float2half_rn(x[i]);
}

// ---------------------------------------------------------------------------
// fp16 HMMA GEMM: C = (Ahi [+ Alo]) @ Wh^T + bias.  TWO=true adds the Alo pass
// (W tile shared). 128x128 tile, K-chunk 32, 3-stage cp.async pipeline.
// ---------------------------------------------------------------------------
struct GemmArgs {
    const half *Ahi, *Alo, *Wh;
    const float* bias;
    float* Cf;
    half* Cq;
};
struct GemmArgs3 { GemmArgs a[3]; };

template <bool TWO>
__global__ void __launch_bounds__(256, 2) gemm_mma_kernel(GemmArgs3 args)
{
    constexpr int PA = 40;
    constexpr int BUFE = 128 * PA;              // 5120 halves per sub-tile
    constexpr int NB = TWO ? 3 : 2;
    constexpr int STAGE = NB * BUFE;
    extern __shared__ __align__(16) half gsm[];

    const GemmArgs ga = args.a[blockIdx.z];

    const int tid = threadIdx.x;
    const int w = tid >> 5, lane = tid & 31, gid = lane >> 2, tig = lane & 3;
    const int bm = blockIdx.y * 128, bn = blockIdx.x * 128;
    const int m0 = (w >> 1) * 32, n0 = (w & 1) * 64;

    float c[2][8][4] = {};

    auto load_chunk = [&](int t, int buf) {
        int kc = t << 5;
        half* sAh = gsm + buf * STAGE;
        half* sW  = sAh + (NB - 1) * BUFE;
#pragma unroll
        for (int i = 0; i < 2; ++i) {
            int idx = tid * 2 + i;           // 0..511
            int row = idx >> 2, q = idx & 3;
            size_t go = (size_t)row * 1024 + kc + q * 8;
            cp16(smem_u32(&sAh[row * PA + q * 8]), ga.Ahi + (size_t)bm * 1024 + go);
            if (TWO)
                cp16(smem_u32(&sAh[BUFE + row * PA + q * 8]),
                     ga.Alo + (size_t)bm * 1024 + go);
            cp16(smem_u32(&sW[row * PA + q * 8]), ga.Wh + (size_t)bn * 1024 + go);
        }
    };

    load_chunk(0, 0); CP_COMMIT;
    load_chunk(1, 1); CP_COMMIT;

    for (int t = 0; t < 32; ++t) {
        if (t + 2 < 32) { CP_WAIT1; } else { CP_WAIT0; }
        __syncthreads();
        if (t + 2 < 32) { load_chunk(t + 2, (t + 2) % 3); CP_COMMIT; }

        const half* sAh = gsm + (t % 3) * STAGE;
        const half* sAl = sAh + BUFE;
        const half* sW  = sAh + (NB - 1) * BUFE;

#pragma unroll
        for (int ks = 0; ks < 32; ks += 16) {
            uint32_t ah[2][4], al[2][4];
#pragma unroll
            for (int mi = 0; mi < 2; ++mi) {
                int ro = (m0 + mi * 16 + (lane & 15)) * PA + ks + ((lane >> 4) << 3);
                LDSM_X4(ah[mi][0], ah[mi][1], ah[mi][2], ah[mi][3], smem_u32(&sAh[ro]));
                if (TWO)
                    LDSM_X4(al[mi][0], al[mi][1], al[mi][2], al[mi][3],
                            smem_u32(&sAl[ro]));
            }
#pragma unroll
            for (int p = 0; p < 4; ++p) {
                int br = n0 + p * 16 + (lane & 7) + ((lane >> 4) << 3);
                int bc = ks + (((lane >> 3) & 1) << 3);
                uint32_t b0, b1, b2, b3;
                LDSM_X4(b0, b1, b2, b3, smem_u32(&sW[br * PA + bc]));
                mma_hf(c[0][2 * p],     ah[0], b0, b1);
                mma_hf(c[1][2 * p],     ah[1], b0, b1);
                mma_hf(c[0][2 * p + 1], ah[0], b2, b3);
                mma_hf(c[1][2 * p + 1], ah[1], b2, b3);
                if (TWO) {
                    mma_hf(c[0][2 * p],     al[0], b0, b1);
                    mma_hf(c[1][2 * p],     al[1], b0, b1);
                    mma_hf(c[0][2 * p + 1], al[0], b2, b3);
                    mma_hf(c[1][2 * p + 1], al[1], b2, b3);
                }
            }
        }
        __syncthreads();
    }

#pragma unroll
    for (int mi = 0; mi < 2; ++mi) {
#pragma unroll
        for (int ni = 0; ni < 8; ++ni) {
            int r0 = bm + m0 + mi * 16 + gid;
            int col = bn + n0 + ni * 8 + 2 * tig;
            float bv0 = ga.bias[col], bv1 = ga.bias[col + 1];
            float o00 = c[mi][ni][0] + bv0, o01 = c[mi][ni][1] + bv1;
            float o10 = c[mi][ni][2] + bv0, o11 = c[mi][ni][3] + bv1;
            if (ga.Cf) {
                *(float2*)&ga.Cf[(size_t)r0 * 1024 + col] = make_float2(o00, o01);
                *(float2*)&ga.Cf[(size_t)(r0 + 8) * 1024 + col] = make_float2(o10, o11);
            }
            if (ga.Cq) {
                *(uint32_t*)&ga.Cq[(size_t)r0 * 1024 + col]       = pack2h(o00, o01);
                *(uint32_t*)&ga.Cq[(size_t)(r0 + 8) * 1024 + col] = pack2h(o10, o11);
            }
        }
    }
}

// ---------------------------------------------------------------------------
// Two-phase fp16 flash attention, key-split warps:
//   8 warps = 4 q-groups (32 rows) x 2 key-halves (32 keys per 64-chunk).
//   Phase 1: l[row] = sum exp(s/8).  Phase 2: recompute S, write normalized
//   attn, ctx += p@V (P register-resident); pair-sum ctx via smem; fp16 hi/lo.
// ---------------------------------------------------------------------------
__global__ void __launch_bounds__(256) attn_fp16_kernel(
    const half* __restrict__ qf, const half* __restrict__ kf,
    const half* __restrict__ vf, const int* __restrict__ maskg,
    float* __restrict__ attn,
    half* __restrict__ ctxh, half* __restrict__ ctxl)
{
    constexpr int P = 72;
    constexpr int KTILE = 64 * P;        // 4608 halves
    constexpr int CTXP = 66;             // sCtx pitch (floats)
    extern __shared__ __align__(16) half hsm[];
    half* Qs = hsm;                      // 128*72 = 9216
    half* K0 = hsm + 9216;               // 2 K stages
    half* V0 = hsm + 9216 + 2 * KTILE;   // 2 V stages
    int*  sMask = (int*)(hsm + 9216 + 4 * KTILE);   // 2048 ints
    float* sL   = (float*)(sMask + 2048);           // 128 floats
    float* sCtx = (float*)K0;            // 128*66*4 = 33792B, aliases K/V (post-loop)

    const int tid = threadIdx.x;
    const int w = tid >> 5, lane = tid & 31, gid = lane >> 2, tig = lane & 3;
    const int qt = blockIdx.x, h = blockIdx.y, b = blockIdx.z;
    const int q0 = qt * 128;
    const int qg = w >> 1, kh = w & 1;
    const int m0 = qg * 32;              // warp's q-row base
    const int n0k = kh * 32;             // warp's key base within chunk

    if (tid < 128) sL[tid] = 0.f;

    // ---- Q + full mask row ----
    {
        size_t base = (size_t)(b * S_ + q0) * D_ + h * 64;
#pragma unroll
        for (int i = 0; i < 4; ++i) {
            int idx = tid * 4 + i;
            int row = idx >> 3, qq = idx & 7;
            cp16(smem_u32(&Qs[row * P + qq * 8]), qf + base + (size_t)row * D_ + qq * 8);
        }
#pragma unroll
        for (int i = 0; i < 2; ++i) {
            int j = tid * 2 + i;
            cp16(smem_u32(&sMask[j * 4]), maskg + b * S_ + j * 4);
        }
        CP_COMMIT;
    }

    auto load_k = [&](int kt, int buf) {
        size_t kbase = (size_t)(b * S_ + kt * 64) * D_ + h * 64;
        half* Ks_ = K0 + buf * KTILE;
#pragma unroll
        for (int i = 0; i < 2; ++i) {
            int idx = tid * 2 + i;
            int row = idx >> 3, qq = idx & 7;
            cp16(smem_u32(&Ks_[row * P + qq * 8]), kf + kbase + (size_t)row * D_ + qq * 8);
        }
    };
    auto load_kv = [&](int kt, int buf) {
        size_t kbase = (size_t)(b * S_ + kt * 64) * D_ + h * 64;
        half* Ks_ = K0 + buf * KTILE;
        half* Vs_ = V0 + buf * KTILE;
#pragma unroll
        for (int i = 0; i < 2; ++i) {
            int idx = tid * 2 + i;
            int row = idx >> 3, qq = idx & 7;
            size_t go = kbase + (size_t)row * D_ + qq * 8;
            cp16(smem_u32(&Ks_[row * P + qq * 8]), kf + go);
            cp16(smem_u32(&Vs_[row * P + qq * 8]), vf + go);
        }
    };

    // S for this warp: 32 q-rows x its 32-key half
    auto computeS = [&](const half* Ks_, float sc[2][4][4]) {
#pragma unroll
        for (int ks = 0; ks < 64; ks += 16) {
            uint32_t a[2][4];
#pragma unroll
            for (int mi = 0; mi < 2; ++mi)
                LDSM_X4(a[mi][0], a[mi][1], a[mi][2], a[mi][3],
                        smem_u32(&Qs[(m0 + mi * 16 + (lane & 15)) * P + ks
                                     + ((lane >> 4) << 3)]));
#pragma unroll
            for (int p = 0; p < 2; ++p) {
                int br = n0k + p * 16 + (lane & 7) + ((lane >> 4) << 3);
                int bc = ks + (((lane >> 3) & 1) << 3);
                uint32_t b0, b1, b2, b3;
                LDSM_X4(b0, b1, b2, b3, smem_u32(&Ks_[br * P + bc]));
#pragma unroll
                for (int mi = 0; mi < 2; ++mi) {
                    mma_hf(sc[mi][2 * p],     a[mi], b0, b1);
                    mma_hf(sc[mi][2 * p + 1], a[mi], b2, b3);
                }
            }
        }
    };

    // ================= phase 1: l =================
    load_k(0, 0); CP_COMMIT;
    float lacc[2][2] = {};

    for (int kt = 0; kt < 32; ++kt) {
        const int buf = kt & 1;
        if (kt + 1 < 32) { load_k(kt + 1, buf ^ 1); CP_COMMIT; CP_WAIT1; }
        else             { CP_WAIT0; }
        __syncthreads();

        float sc[2][4][4] = {};
        computeS(K0 + buf * KTILE, sc);

        const int* mk = sMask + kt * 64;
#pragma unroll
        for (int mi = 0; mi < 2; ++mi)
#pragma unroll
            for (int ni = 0; ni < 4; ++ni) {
                int cc = n0k + ni * 8 + 2 * tig;
                bool k0m = mk[cc] != 0, k1m = mk[cc + 1] != 0;
                lacc[mi][0] += (k0m ? __expf(sc[mi][ni][0] * 0.125f) : 0.f)
                             + (k1m ? __expf(sc[mi][ni][1] * 0.125f) : 0.f);
                lacc[mi][1] += (k0m ? __expf(sc[mi][ni][2] * 0.125f) : 0.f)
                             + (k1m ? __expf(sc[mi][ni][3] * 0.125f) : 0.f);
            }
        __syncthreads();
    }

#pragma unroll
    for (int mi = 0; mi < 2; ++mi)
#pragma unroll
        for (int hf = 0; hf < 2; ++hf) {
            float v = lacc[mi][hf];
            v += __shfl_xor_sync(0xffffffffu, v, 1);
            v += __shfl_xor_sync(0xffffffffu, v, 2);
            if (tig == 0) atomicAdd(&sL[m0 + mi * 16 + gid + hf * 8], v);
        }
    __syncthreads();

    float invl[2][2];
#pragma unroll
    for (int mi = 0; mi < 2; ++mi)
#pragma unroll
        for (int hf = 0; hf < 2; ++hf) {
            float lv = sL[m0 + mi * 16 + gid + hf * 8];
            invl[mi][hf] = (lv > 0.f) ? (1.f / lv) : 0.f;
        }

    // ================= phase 2: attn + ctx =================
    load_kv(0, 0); CP_COMMIT;

    float ctxc[2][8][4] = {};

    for (int kt = 0; kt < 32; ++kt) {
        const int kb = kt * 64;
        const int buf = kt & 1;
        if (kt + 1 < 32) { load_kv(kt + 1, buf ^ 1); CP_COMMIT; CP_WAIT1; }
        else             { CP_WAIT0; }
        __syncthreads();

        const half* Ks_ = K0 + buf * KTILE;
        const half* Vs_ = V0 + buf * KTILE;

        float sc[2][4][4] = {};
        computeS(Ks_, sc);

        const int* mk = sMask + kt * 64;
        uint32_t ah[2][2][4];
#pragma unroll
        for (int mi = 0; mi < 2; ++mi)
#pragma unroll
            for (int ni = 0; ni < 4; ++ni) {
                int cc = n0k + ni * 8 + 2 * tig;
                bool k0m = mk[cc] != 0, k1m = mk[cc + 1] != 0;
                float p00 = k0m ? (__expf(sc[mi][ni][0] * 0.125f) * invl[mi][0]) : 0.f;
                float p01 = k1m ? (__expf(sc[mi][ni][1] * 0.125f) * invl[mi][0]) : 0.f;
                float p10 = k0m ? (__expf(sc[mi][ni][2] * 0.125f) * invl[mi][1]) : 0.f;
                float p11 = k1m ? (__expf(sc[mi][ni][3] * 0.125f) * invl[mi][1]) : 0.f;
                if (attn) {
                    size_t arow = ((size_t)((b * H_ + h) * S_) + q0 + m0 + mi * 16 + gid)
                                  * S_ + kb + cc;
                    *(float2*)&attn[arow]                  = make_float2(p00, p01);
                    *(float2*)&attn[arow + 8 * (size_t)S_] = make_float2(p10, p11);
                }
                int kt2 = ni >> 1, bse = (ni & 1) * 2;
                ah[mi][kt2][bse]     = pack2h(p00, p01);
                ah[mi][kt2][bse + 1] = pack2h(p10, p11);
            }

#pragma unroll
        for (int kt2 = 0; kt2 < 2; ++kt2)
#pragma unroll
            for (int nj = 0; nj < 8; ++nj) {
                uint32_t b0, b1;
                LDSM_X2T(b0, b1,
                         smem_u32(&Vs_[(n0k + kt2 * 16 + (lane & 15)) * P + nj * 8]));
                mma_hf(ctxc[0][nj], ah[0][kt2], b0, b1);
                mma_hf(ctxc[1][nj], ah[1][kt2], b0, b1);
            }
        __syncthreads();
    }

    // ---- pair-sum ctx across key-halves, write fp16 hi/lo ----
    if (kh == 1) {
#pragma unroll
        for (int mi = 0; mi < 2; ++mi)
#pragma unroll
            for (int nj = 0; nj < 8; ++nj) {
                int r = m0 + mi * 16 + gid;
                int cl = nj * 8 + 2 * tig;
                *(float2*)&sCtx[r * CTXP + cl] =
                    make_float2(ctxc[mi][nj][0], ctxc[mi][nj][1]);
                *(float2*)&sCtx[(r + 8) * CTXP + cl] =
                    make_float2(ctxc[mi][nj][2], ctxc[mi][nj][3]);
            }
    }
    __syncthreads();
    if (kh == 0) {
#pragma unroll
        for (int mi = 0; mi < 2; ++mi)
#pragma unroll
            for (int nj = 0; nj < 8; ++nj) {
                int rl = m0 + mi * 16 + gid;
                int cl = nj * 8 + 2 * tig;
                float2 o0 = *(float2*)&sCtx[rl * CTXP + cl];
                float2 o1 = *(float2*)&sCtx[(rl + 8) * CTXP + cl];
                float v00 = ctxc[mi][nj][0] + o0.x, v01 = ctxc[mi][nj][1] + o0.y;
                float v10 = ctxc[mi][nj][2] + o1.x, v11 = ctxc[mi][nj][3] + o1.y;
                int r = q0 + rl;
                int col = h * 64 + cl;
                size_t base = ((size_t)(b * S_) + r) * D_ + col;
                float h00 = __half2float(__float2half_rn(v00));
                float h01 = __half2float(__float2half_rn(v01));
                float h10 = __half2float(__float2half_rn(v10));
                float h11 = __half2float(__float2half_rn(v11));
                *(uint32_t*)&ctxh[base]                  = pack2h(v00, v01);
                *(uint32_t*)&ctxh[base + 8 * (size_t)D_] = pack2h(v10, v11);
                *(uint32_t*)&ctxl[base]                  = pack2h(v00 - h00, v01 - h01);
                *(uint32_t*)&ctxl[base + 8 * (size_t)D_] = pack2h(v10 - h10, v11 - h11);
            }
    }
}

// ---------------------------------------------------------------------------
extern "C" void kernel_launch(void* const* d_in, const int* in_sizes, int n_in,
                              void* d_out, int out_size)
{
    const float* hs   = (const float*)d_in[0];
    const int*   mask = (const int*)  d_in[1];
    const float* Wq   = (const float*)d_in[2];
    const float* bq   = (const float*)d_in[3];
    const float* Wk   = (const float*)d_in[4];
    const float* bk   = (const float*)d_in[5];
    const float* Wv   = (const float*)d_in[6];
    const float* bv   = (const float*)d_in[7];
    const float* Wo   = (const float*)d_in[8];
    const float* bo   = (const float*)d_in[9];

    float* outp = (float*)d_out;

    half *ahp, *qfp, *kfp, *vfp, *chp, *clp, *wqp, *wkp, *wvp, *wop;
    cudaGetSymbolAddress((void**)&ahp, g_ah);
    cudaGetSymbolAddress((void**)&qfp, g_qf);
    cudaGetSymbolAddress((void**)&kfp, g_kf);
    cudaGetSymbolAddress((void**)&vfp, g_vf);
    cudaGetSymbolAddress((void**)&chp, g_ch);
    cudaGetSymbolAddress((void**)&clp, g_cl);
    cudaGetSymbolAddress((void**)&wqp, g_wq);
    cudaGetSymbolAddress((void**)&wkp, g_wk);
    cudaGetSymbolAddress((void**)&wvp, g_wv);
    cudaGetSymbolAddress((void**)&wop, g_wo);

    float* attnp = nullptr;
    if ((long long)out_size >= OUT_ELEMS + ATTN_ELEMS)
        attnp = outp + OUT_ELEMS;

    // 1. casts to fp16
    cast_h_kernel<<<(M_ * D_ + 255) / 256, 256>>>(hs, ahp, M_ * D_);
    cast_h_kernel<<<(D_ * D_ + 255) / 256, 256>>>(Wq, wqp, D_ * D_);
    cast_h_kernel<<<(D_ * D_ + 255) / 256, 256>>>(Wk, wkp, D_ * D_);
    cast_h_kernel<<<(D_ * D_ + 255) / 256, 256>>>(Wv, wvp, D_ * D_);
    cast_h_kernel<<<(D_ * D_ + 255) / 256, 256>>>(Wo, wop, D_ * D_);

    const int smem1 = 3 * 2 * 128 * 40 * (int)sizeof(half);   // 61440 (1-pass)
    const int smem2 = 3 * 3 * 128 * 40 * (int)sizeof(half);   // 92160 (2-pass)
    cudaFuncSetAttribute(gemm_mma_kernel<false>,
                         cudaFuncAttributeMaxDynamicSharedMemorySize, smem1);
    cudaFuncSetAttribute(gemm_mma_kernel<true>,
                         cudaFuncAttributeMaxDynamicSharedMemorySize, smem2);

    // 2. fused Q/K/V projections (1-pass fp16)
    {
        GemmArgs3 a3;
        a3.a[0] = {ahp, nullptr, wqp, bq, nullptr, qfp};
        a3.a[1] = {ahp, nullptr, wkp, bk, nullptr, kfp};
        a3.a[2] = {ahp, nullptr, wvp, bv, nullptr, vfp};
        dim3 gg(D_ / 128, M_ / 128, 3);
        gemm_mma_kernel<false><<<gg, 256, smem1>>>(a3);
    }

    // 3. two-phase fp16 attention (key-split warps; normalized attn; hi/lo ctx)
    {
        dim3 ga(S_ / 128, H_, B_);
        int smA = (9216 + 4 * 4608) * (int)sizeof(half)
                  + 2048 * (int)sizeof(int) + 128 * (int)sizeof(float);
        cudaFuncSetAttribute(attn_fp16_kernel,
                             cudaFuncAttributeMaxDynamicSharedMemorySize, smA);
        attn_fp16_kernel<<<ga, 256, smA>>>(qfp, kfp, vfp, mask, attnp, chp, clp);
    }

    // 4. output projection (2-pass: ctx hi + lo)
    {
        GemmArgs3 a3;
        a3.a[0] = {chp, clp, wop, bo, outp, nullptr};
        dim3 gg(D_ / 128, M_ / 128, 1);
        gemm_mma_kernel<true><<<gg, 256, smem2>>>(a3);
    }
}

// round 9
// speedup vs baseline: 2.1883x; 1.0079x over previous
#include <cuda_runtime.h>
#include <cuda_fp16.h>
#include <cstdint>

namespace {
constexpr int B_  = 4;
constexpr int S_  = 2048;
constexpr int D_  = 1024;
constexpr int H_  = 16;
constexpr int M_  = B_ * S_;  // 8192
constexpr long long OUT_ELEMS  = (long long)M_ * D_;
constexpr long long ATTN_ELEMS = (long long)B_ * H_ * S_ * S_;
}

// ------------------------- device scratch (no allocs) -----------------------
__device__ half g_ah[M_ * D_];
__device__ half g_qf[M_ * D_], g_kf[M_ * D_], g_vf[M_ * D_];
__device__ half g_ch[M_ * D_], g_cl[M_ * D_];
__device__ half g_wq[D_ * D_], g_wk[D_ * D_], g_wv[D_ * D_], g_wo[D_ * D_];

// ----------------------------- helpers --------------------------------------
__device__ __forceinline__ uint32_t smem_u32(const void* p) {
    uint32_t a;
    asm("{ .reg .u64 t; cvta.to.shared.u64 t, %1; cvt.u32.u64 %0, t; }"
        : "=r"(a) : "l"(p));
    return a;
}

__device__ __forceinline__ void cp16(uint32_t s, const void* g) {
    asm volatile("cp.async.cg.shared.global [%0], [%1], 16;" :: "r"(s), "l"(g));
}
#define CP_COMMIT asm volatile("cp.async.commit_group;" ::: "memory")
#define CP_WAIT0  asm volatile("cp.async.wait_group 0;" ::: "memory")
#define CP_WAIT1  asm volatile("cp.async.wait_group 1;" ::: "memory")

#define LDSM_X4(r0, r1, r2, r3, addr) \
    asm volatile("ldmatrix.sync.aligned.m8n8.x4.shared.b16 {%0,%1,%2,%3}, [%4];" \
                 : "=r"(r0), "=r"(r1), "=r"(r2), "=r"(r3) : "r"(addr))

#define LDSM_X2T(r0, r1, addr) \
    asm volatile("ldmatrix.sync.aligned.m8n8.x2.trans.shared.b16 {%0,%1}, [%2];" \
                 : "=r"(r0), "=r"(r1) : "r"(addr))

__device__ __forceinline__ void mma_hf(float c[4], const uint32_t a[4],
                                       uint32_t b0, uint32_t b1) {
    asm volatile(
        "mma.sync.aligned.m16n8k16.row.col.f32.f16.f16.f32 "
        "{%0,%1,%2,%3}, {%4,%5,%6,%7}, {%8,%9}, {%0,%1,%2,%3};"
        : "+f"(c[0]), "+f"(c[1]), "+f"(c[2]), "+f"(c[3])
        : "r"(a[0]), "r"(a[1]), "r"(a[2]), "r"(a[3]), "r"(b0), "r"(b1));
}

__device__ __forceinline__ uint32_t pack2h(float x, float y) {
    __half2 t = __floats2half2_rn(x, y);
    return *reinterpret_cast<uint32_t*>(&t);
}

// ---------------------------------------------------------------------------
// Fused fp32 -> fp16 cast of hidden_states + 4 weight matrices.
// idx < 2^23 -> A; else weight (j >> 20 selects, D_*D_ = 2^20).
// ---------------------------------------------------------------------------
__global__ void cast_all_kernel(const float* __restrict__ hs,
                                const float* __restrict__ Wq,
                                const float* __restrict__ Wk,
                                const float* __restrict__ Wv,
                                const float* __restrict__ Wo,
                                half* __restrict__ ah,
                                half* __restrict__ wq, half* __restrict__ wk,
                                half* __restrict__ wv, half* __restrict__ wo)
{
    int i = blockIdx.x * blockDim.x + threadIdx.x;
    constexpr int MD = M_ * D_;           // 2^23
    constexpr int DD = D_ * D_;           // 2^20
    if (i < MD) {
        ah[i] = __float2half_rn(hs[i]);
    } else {
        int j = i - MD;
        int wsel = j >> 20;
        int off = j & (DD - 1);
        const float* src = (wsel == 0) ? Wq : (wsel == 1) ? Wk
                         : (wsel == 2) ? Wv : Wo;
        half* dst = (wsel == 0) ? wq : (wsel == 1) ? wk
                  : (wsel == 2) ? wv : wo;
        dst[off] = __float2half_rn(src[off]);
    }
}

// ---------------------------------------------------------------------------
// fp16 HMMA GEMM: C = (Ahi [+ Alo]) @ Wh^T + bias.  TWO=true adds the Alo pass
// (W tile shared). 128x128 tile, K-chunk 32, 3-stage cp.async pipeline.
// ---------------------------------------------------------------------------
struct GemmArgs {
    const half *Ahi, *Alo, *Wh;
    const float* bias;
    float* Cf;
    half* Cq;
};
struct GemmArgs3 { GemmArgs a[3]; };

template <bool TWO>
__global__ void __launch_bounds__(256, 2) gemm_mma_kernel(GemmArgs3 args)
{
    constexpr int PA = 40;
    constexpr int BUFE = 128 * PA;              // 5120 halves per sub-tile
    constexpr int NB = TWO ? 3 : 2;
    constexpr int STAGE = NB * BUFE;
    extern __shared__ __align__(16) half gsm[];

    const GemmArgs ga = args.a[blockIdx.z];

    const int tid = threadIdx.x;
    const int w = tid >> 5, lane = tid & 31, gid = lane >> 2, tig = lane & 3;
    const int bm = blockIdx.y * 128, bn = blockIdx.x * 128;
    const int m0 = (w >> 1) * 32, n0 = (w & 1) * 64;

    float c[2][8][4] = {};

    auto load_chunk = [&](int t, int buf) {
        int kc = t << 5;
        half* sAh = gsm + buf * STAGE;
        half* sW  = sAh + (NB - 1) * BUFE;
#pragma unroll
        for (int i = 0; i < 2; ++i) {
            int idx = tid * 2 + i;           // 0..511
            int row = idx >> 2, q = idx & 3;
            size_t go = (size_t)row * 1024 + kc + q * 8;
            cp16(smem_u32(&sAh[row * PA + q * 8]), ga.Ahi + (size_t)bm * 1024 + go);
            if (TWO)
                cp16(smem_u32(&sAh[BUFE + row * PA + q * 8]),
                     ga.Alo + (size_t)bm * 1024 + go);
            cp16(smem_u32(&sW[row * PA + q * 8]), ga.Wh + (size_t)bn * 1024 + go);
        }
    };

    load_chunk(0, 0); CP_COMMIT;
    load_chunk(1, 1); CP_COMMIT;

    for (int t = 0; t < 32; ++t) {
        if (t + 2 < 32) { CP_WAIT1; } else { CP_WAIT0; }
        __syncthreads();
        if (t + 2 < 32) { load_chunk(t + 2, (t + 2) % 3); CP_COMMIT; }

        const half* sAh = gsm + (t % 3) * STAGE;
        const half* sAl = sAh + BUFE;
        const half* sW  = sAh + (NB - 1) * BUFE;

#pragma unroll
        for (int ks = 0; ks < 32; ks += 16) {
            uint32_t ah[2][4], al[2][4];
#pragma unroll
            for (int mi = 0; mi < 2; ++mi) {
                int ro = (m0 + mi * 16 + (lane & 15)) * PA + ks + ((lane >> 4) << 3);
                LDSM_X4(ah[mi][0], ah[mi][1], ah[mi][2], ah[mi][3], smem_u32(&sAh[ro]));
                if (TWO)
                    LDSM_X4(al[mi][0], al[mi][1], al[mi][2], al[mi][3],
                            smem_u32(&sAl[ro]));
            }
#pragma unroll
            for (int p = 0; p < 4; ++p) {
                int br = n0 + p * 16 + (lane & 7) + ((lane >> 4) << 3);
                int bc = ks + (((lane >> 3) & 1) << 3);
                uint32_t b0, b1, b2, b3;
                LDSM_X4(b0, b1, b2, b3, smem_u32(&sW[br * PA + bc]));
                mma_hf(c[0][2 * p],     ah[0], b0, b1);
                mma_hf(c[1][2 * p],     ah[1], b0, b1);
                mma_hf(c[0][2 * p + 1], ah[0], b2, b3);
                mma_hf(c[1][2 * p + 1], ah[1], b2, b3);
                if (TWO) {
                    mma_hf(c[0][2 * p],     al[0], b0, b1);
                    mma_hf(c[1][2 * p],     al[1], b0, b1);
                    mma_hf(c[0][2 * p + 1], al[0], b2, b3);
                    mma_hf(c[1][2 * p + 1], al[1], b2, b3);
                }
            }
        }
        __syncthreads();
    }

#pragma unroll
    for (int mi = 0; mi < 2; ++mi) {
#pragma unroll
        for (int ni = 0; ni < 8; ++ni) {
            int r0 = bm + m0 + mi * 16 + gid;
            int col = bn + n0 + ni * 8 + 2 * tig;
            float bv0 = ga.bias[col], bv1 = ga.bias[col + 1];
            float o00 = c[mi][ni][0] + bv0, o01 = c[mi][ni][1] + bv1;
            float o10 = c[mi][ni][2] + bv0, o11 = c[mi][ni][3] + bv1;
            if (ga.Cf) {
                *(float2*)&ga.Cf[(size_t)r0 * 1024 + col] = make_float2(o00, o01);
                *(float2*)&ga.Cf[(size_t)(r0 + 8) * 1024 + col] = make_float2(o10, o11);
            }
            if (ga.Cq) {
                *(uint32_t*)&ga.Cq[(size_t)r0 * 1024 + col]       = pack2h(o00, o01);
                *(uint32_t*)&ga.Cq[(size_t)(r0 + 8) * 1024 + col] = pack2h(o10, o11);
            }
        }
    }
}

// ---------------------------------------------------------------------------
// Two-phase fp16 flash attention, low-register layout:
//   q-tile 64/CTA; 8 warps = 4 q-groups (16 rows) x 2 key-halves (32 keys).
//   Phase 1: l[row] = sum exp(s/8).  Phase 2: recompute S, write normalized
//   attn, ctx += p@V (P register-resident); pair-sum ctx via smem; fp16 hi/lo.
//   __launch_bounds__(256,2) keeps regs <= 128 -> 2 CTAs/SM -> 4 warps/SMSP.
// ---------------------------------------------------------------------------
__global__ void __launch_bounds__(256, 2) attn_fp16_kernel(
    const half* __restrict__ qf, const half* __restrict__ kf,
    const half* __restrict__ vf, const int* __restrict__ maskg,
    float* __restrict__ attn,
    half* __restrict__ ctxh, half* __restrict__ ctxl)
{
    constexpr int P = 72;
    constexpr int KTILE = 64 * P;        // 4608 halves
    constexpr int CTXP = 66;             // sCtx pitch (floats)
    extern __shared__ __align__(16) half hsm[];
    half* Qs = hsm;                      // 64*72 = 4608 halves
    half* K0 = hsm + 4608;               // 2 K stages
    half* V0 = hsm + 4608 + 2 * KTILE;   // 2 V stages
    int*  sMask = (int*)(hsm + 4608 + 4 * KTILE);   // 2048 ints
    float* sL   = (float*)(sMask + 2048);           // 64 floats
    float* sCtx = (float*)K0;            // 64*66*4 = 16896B, aliases K (post-loop)

    const int tid = threadIdx.x;
    const int w = tid >> 5, lane = tid & 31, gid = lane >> 2, tig = lane & 3;
    const int qt = blockIdx.x, h = blockIdx.y, b = blockIdx.z;
    const int q0 = qt * 64;
    const int qg = w >> 1, kh = w & 1;
    const int m0 = qg * 16;              // warp's q-row base (16 rows)
    const int n0k = kh * 32;             // warp's key base within chunk

    if (tid < 64) sL[tid] = 0.f;

    // ---- Q (64x64) + full mask row ----
    {
        size_t base = (size_t)(b * S_ + q0) * D_ + h * 64;
#pragma unroll
        for (int i = 0; i < 2; ++i) {
            int idx = tid * 2 + i;       // 0..511
            int row = idx >> 3, qq = idx & 7;
            cp16(smem_u32(&Qs[row * P + qq * 8]), qf + base + (size_t)row * D_ + qq * 8);
        }
#pragma unroll
        for (int i = 0; i < 2; ++i) {
            int j = tid * 2 + i;
            cp16(smem_u32(&sMask[j * 4]), maskg + b * S_ + j * 4);
        }
        CP_COMMIT;
    }

    auto load_k = [&](int kt, int buf) {
        size_t kbase = (size_t)(b * S_ + kt * 64) * D_ + h * 64;
        half* Ks_ = K0 + buf * KTILE;
#pragma unroll
        for (int i = 0; i < 2; ++i) {
            int idx = tid * 2 + i;
            int row = idx >> 3, qq = idx & 7;
            cp16(smem_u32(&Ks_[row * P + qq * 8]), kf + kbase + (size_t)row * D_ + qq * 8);
        }
    };
    auto load_kv = [&](int kt, int buf) {
        size_t kbase = (size_t)(b * S_ + kt * 64) * D_ + h * 64;
        half* Ks_ = K0 + buf * KTILE;
        half* Vs_ = V0 + buf * KTILE;
#pragma unroll
        for (int i = 0; i < 2; ++i) {
            int idx = tid * 2 + i;
            int row = idx >> 3, qq = idx & 7;
            size_t go = kbase + (size_t)row * D_ + qq * 8;
            cp16(smem_u32(&Ks_[row * P + qq * 8]), kf + go);
            cp16(smem_u32(&Vs_[row * P + qq * 8]), vf + go);
        }
    };

    // S for this warp: 16 q-rows x its 32-key half
    auto computeS = [&](const half* Ks_, float sc[4][4]) {
#pragma unroll
        for (int ks = 0; ks < 64; ks += 16) {
            uint32_t a[4];
            LDSM_X4(a[0], a[1], a[2], a[3],
                    smem_u32(&Qs[(m0 + (lane & 15)) * P + ks + ((lane >> 4) << 3)]));
#pragma unroll
            for (int p = 0; p < 2; ++p) {
                int br = n0k + p * 16 + (lane & 7) + ((lane >> 4) << 3);
                int bc = ks + (((lane >> 3) & 1) << 3);
                uint32_t b0, b1, b2, b3;
                LDSM_X4(b0, b1, b2, b3, smem_u32(&Ks_[br * P + bc]));
                mma_hf(sc[2 * p],     a, b0, b1);
                mma_hf(sc[2 * p + 1], a, b2, b3);
            }
        }
    };

    // ================= phase 1: l =================
    load_k(0, 0); CP_COMMIT;
    float lacc[2] = {};

    for (int kt = 0; kt < 32; ++kt) {
        const int buf = kt & 1;
        if (kt + 1 < 32) { load_k(kt + 1, buf ^ 1); CP_COMMIT; CP_WAIT1; }
        else             { CP_WAIT0; }
        __syncthreads();

        float sc[4][4] = {};
        computeS(K0 + buf * KTILE, sc);

        const int* mk = sMask + kt * 64;
#pragma unroll
        for (int ni = 0; ni < 4; ++ni) {
            int cc = n0k + ni * 8 + 2 * tig;
            bool k0m = mk[cc] != 0, k1m = mk[cc + 1] != 0;
            lacc[0] += (k0m ? __expf(sc[ni][0] * 0.125f) : 0.f)
                     + (k1m ? __expf(sc[ni][1] * 0.125f) : 0.f);
            lacc[1] += (k0m ? __expf(sc[ni][2] * 0.125f) : 0.f)
                     + (k1m ? __expf(sc[ni][3] * 0.125f) : 0.f);
        }
        __syncthreads();
    }

#pragma unroll
    for (int hf = 0; hf < 2; ++hf) {
        float v = lacc[hf];
        v += __shfl_xor_sync(0xffffffffu, v, 1);
        v += __shfl_xor_sync(0xffffffffu, v, 2);
        if (tig == 0) atomicAdd(&sL[m0 + gid + hf * 8], v);
    }
    __syncthreads();

    float invl[2];
#pragma unroll
    for (int hf = 0; hf < 2; ++hf) {
        float lv = sL[m0 + gid + hf * 8];
        invl[hf] = (lv > 0.f) ? (1.f / lv) : 0.f;
    }

    // ================= phase 2: attn + ctx =================
    load_kv(0, 0); CP_COMMIT;

    float ctxc[8][4] = {};

    for (int kt = 0; kt < 32; ++kt) {
        const int kb = kt * 64;
        const int buf = kt & 1;
        if (kt + 1 < 32) { load_kv(kt + 1, buf ^ 1); CP_COMMIT; CP_WAIT1; }
        else             { CP_WAIT0; }
        __syncthreads();

        const half* Ks_ = K0 + buf * KTILE;
        const half* Vs_ = V0 + buf * KTILE;

        float sc[4][4] = {};
        computeS(Ks_, sc);

        const int* mk = sMask + kt * 64;
        uint32_t ah[2][4];
#pragma unroll
        for (int ni = 0; ni < 4; ++ni) {
            int cc = n0k + ni * 8 + 2 * tig;
            bool k0m = mk[cc] != 0, k1m = mk[cc + 1] != 0;
            float p00 = k0m ? (__expf(sc[ni][0] * 0.125f) * invl[0]) : 0.f;
            float p01 = k1m ? (__expf(sc[ni][1] * 0.125f) * invl[0]) : 0.f;
            float p10 = k0m ? (__expf(sc[ni][2] * 0.125f) * invl[1]) : 0.f;
            float p11 = k1m ? (__expf(sc[ni][3] * 0.125f) * invl[1]) : 0.f;
            if (attn) {
                size_t arow = ((size_t)((b * H_ + h) * S_) + q0 + m0 + gid) * S_ + kb + cc;
                *(float2*)&attn[arow]                  = make_float2(p00, p01);
                *(float2*)&attn[arow + 8 * (size_t)S_] = make_float2(p10, p11);
            }
            int kt2 = ni >> 1, bse = (ni & 1) * 2;
            ah[kt2][bse]     = pack2h(p00, p01);
            ah[kt2][bse + 1] = pack2h(p10, p11);
        }

#pragma unroll
        for (int kt2 = 0; kt2 < 2; ++kt2)
#pragma unroll
            for (int nj = 0; nj < 8; ++nj) {
                uint32_t b0, b1;
                LDSM_X2T(b0, b1,
                         smem_u32(&Vs_[(n0k + kt2 * 16 + (lane & 15)) * P + nj * 8]));
                mma_hf(ctxc[nj], ah[kt2], b0, b1);
            }
        __syncthreads();
    }

    // ---- pair-sum ctx across key-halves, write fp16 hi/lo ----
    if (kh == 1) {
#pragma unroll
        for (int nj = 0; nj < 8; ++nj) {
            int r = m0 + gid;
            int cl = nj * 8 + 2 * tig;
            *(float2*)&sCtx[r * CTXP + cl] = make_float2(ctxc[nj][0], ctxc[nj][1]);
            *(float2*)&sCtx[(r + 8) * CTXP + cl] = make_float2(ctxc[nj][2], ctxc[nj][3]);
        }
    }
    __syncthreads();
    if (kh == 0) {
#pragma unroll
        for (int nj = 0; nj < 8; ++nj) {
            int rl = m0 + gid;
            int cl = nj * 8 + 2 * tig;
            float2 o0 = *(float2*)&sCtx[rl * CTXP + cl];
            float2 o1 = *(float2*)&sCtx[(rl + 8) * CTXP + cl];
            float v00 = ctxc[nj][0] + o0.x, v01 = ctxc[nj][1] + o0.y;
            float v10 = ctxc[nj][2] + o1.x, v11 = ctxc[nj][3] + o1.y;
            int r = q0 + rl;
            int col = h * 64 + cl;
            size_t base = ((size_t)(b * S_) + r) * D_ + col;
            float h00 = __half2float(__float2half_rn(v00));
            float h01 = __half2float(__float2half_rn(v01));
            float h10 = __half2float(__float2half_rn(v10));
            float h11 = __half2float(__float2half_rn(v11));
            *(uint32_t*)&ctxh[base]                  = pack2h(v00, v01);
            *(uint32_t*)&ctxh[base + 8 * (size_t)D_] = pack2h(v10, v11);
            *(uint32_t*)&ctxl[base]                  = pack2h(v00 - h00, v01 - h01);
            *(uint32_t*)&ctxl[base + 8 * (size_t)D_] = pack2h(v10 - h10, v11 - h11);
        }
    }
}

// ---------------------------------------------------------------------------
extern "C" void kernel_launch(void* const* d_in, const int* in_sizes, int n_in,
                              void* d_out, int out_size)
{
    const float* hs   = (const float*)d_in[0];
    const int*   mask = (const int*)  d_in[1];
    const float* Wq   = (const float*)d_in[2];
    const float* bq   = (const float*)d_in[3];
    const float* Wk   = (const float*)d_in[4];
    const float* bk   = (const float*)d_in[5];
    const float* Wv   = (const float*)d_in[6];
    const float* bv   = (const float*)d_in[7];
    const float* Wo   = (const float*)d_in[8];
    const float* bo   = (const float*)d_in[9];

    float* outp = (float*)d_out;

    half *ahp, *qfp, *kfp, *vfp, *chp, *clp, *wqp, *wkp, *wvp, *wop;
    cudaGetSymbolAddress((void**)&ahp, g_ah);
    cudaGetSymbolAddress((void**)&qfp, g_qf);
    cudaGetSymbolAddress((void**)&kfp, g_kf);
    cudaGetSymbolAddress((void**)&vfp, g_vf);
    cudaGetSymbolAddress((void**)&chp, g_ch);
    cudaGetSymbolAddress((void**)&clp, g_cl);
    cudaGetSymbolAddress((void**)&wqp, g_wq);
    cudaGetSymbolAddress((void**)&wkp, g_wk);
    cudaGetSymbolAddress((void**)&wvp, g_wv);
    cudaGetSymbolAddress((void**)&wop, g_wo);

    float* attnp = nullptr;
    if ((long long)out_size >= OUT_ELEMS + ATTN_ELEMS)
        attnp = outp + OUT_ELEMS;

    // 1. fused casts to fp16
    {
        int n = M_ * D_ + 4 * D_ * D_;
        cast_all_kernel<<<(n + 255) / 256, 256>>>(hs, Wq, Wk, Wv, Wo,
                                                  ahp, wqp, wkp, wvp, wop);
    }

    const int smem1 = 3 * 2 * 128 * 40 * (int)sizeof(half);   // 61440 (1-pass)
    const int smem2 = 3 * 3 * 128 * 40 * (int)sizeof(half);   // 92160 (2-pass)
    cudaFuncSetAttribute(gemm_mma_kernel<false>,
                         cudaFuncAttributeMaxDynamicSharedMemorySize, smem1);
    cudaFuncSetAttribute(gemm_mma_kernel<true>,
                         cudaFuncAttributeMaxDynamicSharedMemorySize, smem2);

    // 2. fused Q/K/V projections (1-pass fp16)
    {
        GemmArgs3 a3;
        a3.a[0] = {ahp, nullptr, wqp, bq, nullptr, qfp};
        a3.a[1] = {ahp, nullptr, wkp, bk, nullptr, kfp};
        a3.a[2] = {ahp, nullptr, wvp, bv, nullptr, vfp};
        dim3 gg(D_ / 128, M_ / 128, 3);
        gemm_mma_kernel<false><<<gg, 256, smem1>>>(a3);
    }

    // 3. two-phase fp16 attention (low-register; q-tile 64)
    {
        dim3 ga(S_ / 64, H_, B_);
        int smA = (4608 + 4 * 4608) * (int)sizeof(half)
                  + 2048 * (int)sizeof(int) + 64 * (int)sizeof(float);
        cudaFuncSetAttribute(attn_fp16_kernel,
                             cudaFuncAttributeMaxDynamicSharedMemorySize, smA);
        attn_fp16_kernel<<<ga, 256, smA>>>(qfp, kfp, vfp, mask, attnp, chp, clp);
    }

    // 4. output projection (2-pass: ctx hi + lo)
    {
        GemmArgs3 a3;
        a3.a[0] = {chp, clp, wop, bo, outp, nullptr};
        dim3 gg(D_ / 128, M_ / 128, 1);
        gemm_mma_kernel<true><<<gg, 256, smem2>>>(a3);
    }
}

// round 10
// speedup vs baseline: 2.2070x; 1.0085x over previous
#include <cuda_runtime.h>
#include <cuda_fp16.h>
#include <cstdint>

namespace {
constexpr int B_  = 4;
constexpr int S_  = 2048;
constexpr int D_  = 1024;
constexpr int H_  = 16;
constexpr int M_  = B_ * S_;  // 8192
constexpr long long OUT_ELEMS  = (long long)M_ * D_;
constexpr long long ATTN_ELEMS = (long long)B_ * H_ * S_ * S_;
}

// ------------------------- device scratch (no allocs) -----------------------
__device__ half g_ah[M_ * D_];
__device__ half g_qf[M_ * D_], g_kf[M_ * D_], g_vf[M_ * D_];
__device__ half g_ch[M_ * D_], g_cl[M_ * D_];
__device__ half g_wq[D_ * D_], g_wk[D_ * D_], g_wv[D_ * D_], g_wo[D_ * D_];

// ----------------------------- helpers --------------------------------------
__device__ __forceinline__ uint32_t smem_u32(const void* p) {
    uint32_t a;
    asm("{ .reg .u64 t; cvta.to.shared.u64 t, %1; cvt.u32.u64 %0, t; }"
        : "=r"(a) : "l"(p));
    return a;
}

__device__ __forceinline__ void cp16(uint32_t s, const void* g) {
    asm volatile("cp.async.cg.shared.global [%0], [%1], 16;" :: "r"(s), "l"(g));
}
#define CP_COMMIT asm volatile("cp.async.commit_group;" ::: "memory")
#define CP_WAIT0  asm volatile("cp.async.wait_group 0;" ::: "memory")
#define CP_WAIT1  asm volatile("cp.async.wait_group 1;" ::: "memory")

#define LDSM_X4(r0, r1, r2, r3, addr) \
    asm volatile("ldmatrix.sync.aligned.m8n8.x4.shared.b16 {%0,%1,%2,%3}, [%4];" \
                 : "=r"(r0), "=r"(r1), "=r"(r2), "=r"(r3) : "r"(addr))

#define LDSM_X4T(r0, r1, r2, r3, addr) \
    asm volatile("ldmatrix.sync.aligned.m8n8.x4.trans.shared.b16 {%0,%1,%2,%3}, [%4];" \
                 : "=r"(r0), "=r"(r1), "=r"(r2), "=r"(r3) : "r"(addr))

__device__ __forceinline__ void mma_hf(float c[4], const uint32_t a[4],
                                       uint32_t b0, uint32_t b1) {
    asm volatile(
        "mma.sync.aligned.m16n8k16.row.col.f32.f16.f16.f32 "
        "{%0,%1,%2,%3}, {%4,%5,%6,%7}, {%8,%9}, {%0,%1,%2,%3};"
        : "+f"(c[0]), "+f"(c[1]), "+f"(c[2]), "+f"(c[3])
        : "r"(a[0]), "r"(a[1]), "r"(a[2]), "r"(a[3]), "r"(b0), "r"(b1));
}

__device__ __forceinline__ uint32_t pack2h(float x, float y) {
    __half2 t = __floats2half2_rn(x, y);
    return *reinterpret_cast<uint32_t*>(&t);
}

// ---------------------------------------------------------------------------
// Fused fp32 -> fp16 cast of hidden_states + 4 weight matrices.
// ---------------------------------------------------------------------------
__global__ void cast_all_kernel(const float* __restrict__ hs,
                                const float* __restrict__ Wq,
                                const float* __restrict__ Wk,
                                const float* __restrict__ Wv,
                                const float* __restrict__ Wo,
                                half* __restrict__ ah,
                                half* __restrict__ wq, half* __restrict__ wk,
                                half* __restrict__ wv, half* __restrict__ wo)
{
    int i = blockIdx.x * blockDim.x + threadIdx.x;
    constexpr int MD = M_ * D_;           // 2^23
    constexpr int DD = D_ * D_;           // 2^20
    if (i < MD) {
        ah[i] = __float2half_rn(hs[i]);
    } else {
        int j = i - MD;
        int wsel = j >> 20;
        int off = j & (DD - 1);
        const float* src = (wsel == 0) ? Wq : (wsel == 1) ? Wk
                         : (wsel == 2) ? Wv : Wo;
        half* dst = (wsel == 0) ? wq : (wsel == 1) ? wk
                  : (wsel == 2) ? wv : wo;
        dst[off] = __float2half_rn(src[off]);
    }
}

// ---------------------------------------------------------------------------
// fp16 HMMA GEMM: C = (Ahi [+ Alo]) @ Wh^T + bias.
// TWO=false: 3-stage pipeline (2 bufs/stage).  TWO=true: 2-stage (3 bufs/stage)
// to keep smem <= 61KB so 2 CTAs/SM co-reside.
// ---------------------------------------------------------------------------
struct GemmArgs {
    const half *Ahi, *Alo, *Wh;
    const float* bias;
    float* Cf;
    half* Cq;
};
struct GemmArgs3 { GemmArgs a[3]; };

template <bool TWO>
__global__ void __launch_bounds__(256, 2) gemm_mma_kernel(GemmArgs3 args)
{
    constexpr int PA = 40;
    constexpr int BUFE = 128 * PA;              // 5120 halves per sub-tile
    constexpr int NB = TWO ? 3 : 2;             // bufs per stage
    constexpr int NSTAGE = TWO ? 2 : 3;
    constexpr int STAGE = NB * BUFE;
    extern __shared__ __align__(16) half gsm[];

    const GemmArgs ga = args.a[blockIdx.z];

    const int tid = threadIdx.x;
    const int w = tid >> 5, lane = tid & 31, gid = lane >> 2, tig = lane & 3;
    const int bm = blockIdx.y * 128, bn = blockIdx.x * 128;
    const int m0 = (w >> 1) * 32, n0 = (w & 1) * 64;

    float c[2][8][4] = {};

    auto load_chunk = [&](int t, int buf) {
        int kc = t << 5;
        half* sAh = gsm + buf * STAGE;
        half* sW  = sAh + (NB - 1) * BUFE;
#pragma unroll
        for (int i = 0; i < 2; ++i) {
            int idx = tid * 2 + i;           // 0..511
            int row = idx >> 2, q = idx & 3;
            size_t go = (size_t)row * 1024 + kc + q * 8;
            cp16(smem_u32(&sAh[row * PA + q * 8]), ga.Ahi + (size_t)bm * 1024 + go);
            if (TWO)
                cp16(smem_u32(&sAh[BUFE + row * PA + q * 8]),
                     ga.Alo + (size_t)bm * 1024 + go);
            cp16(smem_u32(&sW[row * PA + q * 8]), ga.Wh + (size_t)bn * 1024 + go);
        }
    };

    auto compute_chunk = [&](int buf) {
        const half* sAh = gsm + buf * STAGE;
        const half* sAl = sAh + BUFE;
        const half* sW  = sAh + (NB - 1) * BUFE;
#pragma unroll
        for (int ks = 0; ks < 32; ks += 16) {
            uint32_t ah[2][4], al[2][4];
#pragma unroll
            for (int mi = 0; mi < 2; ++mi) {
                int ro = (m0 + mi * 16 + (lane & 15)) * PA + ks + ((lane >> 4) << 3);
                LDSM_X4(ah[mi][0], ah[mi][1], ah[mi][2], ah[mi][3], smem_u32(&sAh[ro]));
                if (TWO)
                    LDSM_X4(al[mi][0], al[mi][1], al[mi][2], al[mi][3],
                            smem_u32(&sAl[ro]));
            }
#pragma unroll
            for (int p = 0; p < 4; ++p) {
                int br = n0 + p * 16 + (lane & 7) + ((lane >> 4) << 3);
                int bc = ks + (((lane >> 3) & 1) << 3);
                uint32_t b0, b1, b2, b3;
                LDSM_X4(b0, b1, b2, b3, smem_u32(&sW[br * PA + bc]));
                mma_hf(c[0][2 * p],     ah[0], b0, b1);
                mma_hf(c[1][2 * p],     ah[1], b0, b1);
                mma_hf(c[0][2 * p + 1], ah[0], b2, b3);
                mma_hf(c[1][2 * p + 1], ah[1], b2, b3);
                if (TWO) {
                    mma_hf(c[0][2 * p],     al[0], b0, b1);
                    mma_hf(c[1][2 * p],     al[1], b0, b1);
                    mma_hf(c[0][2 * p + 1], al[0], b2, b3);
                    mma_hf(c[1][2 * p + 1], al[1], b2, b3);
                }
            }
        }
    };

    load_chunk(0, 0); CP_COMMIT;
    load_chunk(1, 1); CP_COMMIT;

    if (TWO) {
        // 2-stage double buffer: prefetch after compute (buffer reuse).
        for (int t = 0; t < 32; ++t) {
            if (t + 2 < 32) { CP_WAIT1; } else { CP_WAIT0; }
            __syncthreads();
            compute_chunk(t & 1);
            __syncthreads();
            if (t + 2 < 32) { load_chunk(t + 2, t & 1); CP_COMMIT; }
        }
    } else {
        for (int t = 0; t < 32; ++t) {
            if (t + 2 < 32) { CP_WAIT1; } else { CP_WAIT0; }
            __syncthreads();
            if (t + 2 < 32) { load_chunk(t + 2, (t + 2) % 3); CP_COMMIT; }
            compute_chunk(t % 3);
            __syncthreads();
        }
    }

#pragma unroll
    for (int mi = 0; mi < 2; ++mi) {
#pragma unroll
        for (int ni = 0; ni < 8; ++ni) {
            int r0 = bm + m0 + mi * 16 + gid;
            int col = bn + n0 + ni * 8 + 2 * tig;
            float bv0 = ga.bias[col], bv1 = ga.bias[col + 1];
            float o00 = c[mi][ni][0] + bv0, o01 = c[mi][ni][1] + bv1;
            float o10 = c[mi][ni][2] + bv0, o11 = c[mi][ni][3] + bv1;
            if (ga.Cf) {
                *(float2*)&ga.Cf[(size_t)r0 * 1024 + col] = make_float2(o00, o01);
                *(float2*)&ga.Cf[(size_t)(r0 + 8) * 1024 + col] = make_float2(o10, o11);
            }
            if (ga.Cq) {
                *(uint32_t*)&ga.Cq[(size_t)r0 * 1024 + col]       = pack2h(o00, o01);
                *(uint32_t*)&ga.Cq[(size_t)(r0 + 8) * 1024 + col] = pack2h(o10, o11);
            }
        }
    }
}

// ---------------------------------------------------------------------------
// Two-phase fp16 flash attention (q-tile 64; 8 warps = 4 q-groups x 2 key-halves)
// ---------------------------------------------------------------------------
__global__ void __launch_bounds__(256, 2) attn_fp16_kernel(
    const half* __restrict__ qf, const half* __restrict__ kf,
    const half* __restrict__ vf, const int* __restrict__ maskg,
    float* __restrict__ attn,
    half* __restrict__ ctxh, half* __restrict__ ctxl)
{
    constexpr int P = 72;
    constexpr int KTILE = 64 * P;        // 4608 halves
    constexpr int CTXP = 66;             // sCtx pitch (floats)
    extern __shared__ __align__(16) half hsm[];
    half* Qs = hsm;                      // 64*72 = 4608 halves
    half* K0 = hsm + 4608;               // 2 K stages
    half* V0 = hsm + 4608 + 2 * KTILE;   // 2 V stages
    int*  sMask = (int*)(hsm + 4608 + 4 * KTILE);   // 2048 ints
    float* sL   = (float*)(sMask + 2048);           // 64 floats
    float* sCtx = (float*)K0;            // aliases K stages (post-loop)

    const int tid = threadIdx.x;
    const int w = tid >> 5, lane = tid & 31, gid = lane >> 2, tig = lane & 3;
    const int qt = blockIdx.x, h = blockIdx.y, b = blockIdx.z;
    const int q0 = qt * 64;
    const int qg = w >> 1, kh = w & 1;
    const int m0 = qg * 16;
    const int n0k = kh * 32;

    if (tid < 64) sL[tid] = 0.f;

    // ---- Q (64x64) + full mask row ----
    {
        size_t base = (size_t)(b * S_ + q0) * D_ + h * 64;
#pragma unroll
        for (int i = 0; i < 2; ++i) {
            int idx = tid * 2 + i;
            int row = idx >> 3, qq = idx & 7;
            cp16(smem_u32(&Qs[row * P + qq * 8]), qf + base + (size_t)row * D_ + qq * 8);
        }
#pragma unroll
        for (int i = 0; i < 2; ++i) {
            int j = tid * 2 + i;
            cp16(smem_u32(&sMask[j * 4]), maskg + b * S_ + j * 4);
        }
        CP_COMMIT;
    }

    auto load_k = [&](int kt, int buf) {
        size_t kbase = (size_t)(b * S_ + kt * 64) * D_ + h * 64;
        half* Ks_ = K0 + buf * KTILE;
#pragma unroll
        for (int i = 0; i < 2; ++i) {
            int idx = tid * 2 + i;
            int row = idx >> 3, qq = idx & 7;
            cp16(smem_u32(&Ks_[row * P + qq * 8]), kf + kbase + (size_t)row * D_ + qq * 8);
        }
    };
    auto load_kv = [&](int kt, int buf) {
        size_t kbase = (size_t)(b * S_ + kt * 64) * D_ + h * 64;
        half* Ks_ = K0 + buf * KTILE;
        half* Vs_ = V0 + buf * KTILE;
#pragma unroll
        for (int i = 0; i < 2; ++i) {
            int idx = tid * 2 + i;
            int row = idx >> 3, qq = idx & 7;
            size_t go = kbase + (size_t)row * D_ + qq * 8;
            cp16(smem_u32(&Ks_[row * P + qq * 8]), kf + go);
            cp16(smem_u32(&Vs_[row * P + qq * 8]), vf + go);
        }
    };

    auto computeS = [&](const half* Ks_, float sc[4][4]) {
#pragma unroll
        for (int ks = 0; ks < 64; ks += 16) {
            uint32_t a[4];
            LDSM_X4(a[0], a[1], a[2], a[3],
                    smem_u32(&Qs[(m0 + (lane & 15)) * P + ks + ((lane >> 4) << 3)]));
#pragma unroll
            for (int p = 0; p < 2; ++p) {
                int br = n0k + p * 16 + (lane & 7) + ((lane >> 4) << 3);
                int bc = ks + (((lane >> 3) & 1) << 3);
                uint32_t b0, b1, b2, b3;
                LDSM_X4(b0, b1, b2, b3, smem_u32(&Ks_[br * P + bc]));
                mma_hf(sc[2 * p],     a, b0, b1);
                mma_hf(sc[2 * p + 1], a, b2, b3);
            }
        }
    };

    // ================= phase 1: l =================
    load_k(0, 0); CP_COMMIT;
    float lacc[2] = {};

    for (int kt = 0; kt < 32; ++kt) {
        const int buf = kt & 1;
        if (kt + 1 < 32) { load_k(kt + 1, buf ^ 1); CP_COMMIT; CP_WAIT1; }
        else             { CP_WAIT0; }
        __syncthreads();

        float sc[4][4] = {};
        computeS(K0 + buf * KTILE, sc);

        const int* mk = sMask + kt * 64;
#pragma unroll
        for (int ni = 0; ni < 4; ++ni) {
            int cc = n0k + ni * 8 + 2 * tig;
            bool k0m = mk[cc] != 0, k1m = mk[cc + 1] != 0;
            lacc[0] += (k0m ? __expf(sc[ni][0] * 0.125f) : 0.f)
                     + (k1m ? __expf(sc[ni][1] * 0.125f) : 0.f);
            lacc[1] += (k0m ? __expf(sc[ni][2] * 0.125f) : 0.f)
                     + (k1m ? __expf(sc[ni][3] * 0.125f) : 0.f);
        }
        __syncthreads();
    }

#pragma unroll
    for (int hf = 0; hf < 2; ++hf) {
        float v = lacc[hf];
        v += __shfl_xor_sync(0xffffffffu, v, 1);
        v += __shfl_xor_sync(0xffffffffu, v, 2);
        if (tig == 0) atomicAdd(&sL[m0 + gid + hf * 8], v);
    }
    __syncthreads();

    float invl[2];
#pragma unroll
    for (int hf = 0; hf < 2; ++hf) {
        float lv = sL[m0 + gid + hf * 8];
        invl[hf] = (lv > 0.f) ? (1.f / lv) : 0.f;
    }

    // ================= phase 2: attn + ctx =================
    load_kv(0, 0); CP_COMMIT;

    float ctxc[8][4] = {};

    for (int kt = 0; kt < 32; ++kt) {
        const int kb = kt * 64;
        const int buf = kt & 1;
        if (kt + 1 < 32) { load_kv(kt + 1, buf ^ 1); CP_COMMIT; CP_WAIT1; }
        else             { CP_WAIT0; }
        __syncthreads();

        const half* Ks_ = K0 + buf * KTILE;
        const half* Vs_ = V0 + buf * KTILE;

        float sc[4][4] = {};
        computeS(Ks_, sc);

        const int* mk = sMask + kt * 64;
        uint32_t ah[2][4];
#pragma unroll
        for (int ni = 0; ni < 4; ++ni) {
            int cc = n0k + ni * 8 + 2 * tig;
            bool k0m = mk[cc] != 0, k1m = mk[cc + 1] != 0;
            float p00 = k0m ? (__expf(sc[ni][0] * 0.125f) * invl[0]) : 0.f;
            float p01 = k1m ? (__expf(sc[ni][1] * 0.125f) * invl[0]) : 0.f;
            float p10 = k0m ? (__expf(sc[ni][2] * 0.125f) * invl[1]) : 0.f;
            float p11 = k1m ? (__expf(sc[ni][3] * 0.125f) * invl[1]) : 0.f;
            if (attn) {
                size_t arow = ((size_t)((b * H_ + h) * S_) + q0 + m0 + gid) * S_ + kb + cc;
                *(float2*)&attn[arow]                  = make_float2(p00, p01);
                *(float2*)&attn[arow + 8 * (size_t)S_] = make_float2(p10, p11);
            }
            int kt2 = ni >> 1, bse = (ni & 1) * 2;
            ah[kt2][bse]     = pack2h(p00, p01);
            ah[kt2][bse + 1] = pack2h(p10, p11);
        }

        // ctx += P @ V  (x4.trans: 2 n-groups per ldmatrix)
#pragma unroll
        for (int kt2 = 0; kt2 < 2; ++kt2)
#pragma unroll
            for (int nj = 0; nj < 8; nj += 2) {
                uint32_t b0, b1, b2, b3;
                LDSM_X4T(b0, b1, b2, b3,
                         smem_u32(&Vs_[(n0k + kt2 * 16 + (lane & 15)) * P
                                       + (nj + (lane >> 4)) * 8]));
                mma_hf(ctxc[nj],     ah[kt2], b0, b1);
                mma_hf(ctxc[nj + 1], ah[kt2], b2, b3);
            }
        __syncthreads();
    }

    // ---- pair-sum ctx across key-halves, write fp16 hi/lo ----
    if (kh == 1) {
#pragma unroll
        for (int nj = 0; nj < 8; ++nj) {
            int r = m0 + gid;
            int cl = nj * 8 + 2 * tig;
            *(float2*)&sCtx[r * CTXP + cl] = make_float2(ctxc[nj][0], ctxc[nj][1]);
            *(float2*)&sCtx[(r + 8) * CTXP + cl] = make_float2(ctxc[nj][2], ctxc[nj][3]);
        }
    }
    __syncthreads();
    if (kh == 0) {
#pragma unroll
        for (int nj = 0; nj < 8; ++nj) {
            int rl = m0 + gid;
            int cl = nj * 8 + 2 * tig;
            float2 o0 = *(float2*)&sCtx[rl * CTXP + cl];
            float2 o1 = *(float2*)&sCtx[(rl + 8) * CTXP + cl];
            float v00 = ctxc[nj][0] + o0.x, v01 = ctxc[nj][1] + o0.y;
            float v10 = ctxc[nj][2] + o1.x, v11 = ctxc[nj][3] + o1.y;
            int r = q0 + rl;
            int col = h * 64 + cl;
            size_t base = ((size_t)(b * S_) + r) * D_ + col;
            float h00 = __half2float(__float2half_rn(v00));
            float h01 = __half2float(__float2half_rn(v01));
            float h10 = __half2float(__float2half_rn(v10));
            float h11 = __half2float(__float2half_rn(v11));
            *(uint32_t*)&ctxh[base]                  = pack2h(v00, v01);
            *(uint32_t*)&ctxh[base + 8 * (size_t)D_] = pack2h(v10, v11);
            *(uint32_t*)&ctxl[base]                  = pack2h(v00 - h00, v01 - h01);
            *(uint32_t*)&ctxl[base + 8 * (size_t)D_] = pack2h(v10 - h10, v11 - h11);
        }
    }
}

// ---------------------------------------------------------------------------
extern "C" void kernel_launch(void* const* d_in, const int* in_sizes, int n_in,
                              void* d_out, int out_size)
{
    const float* hs   = (const float*)d_in[0];
    const int*   mask = (const int*)  d_in[1];
    const float* Wq   = (const float*)d_in[2];
    const float* bq   = (const float*)d_in[3];
    const float* Wk   = (const float*)d_in[4];
    const float* bk   = (const float*)d_in[5];
    const float* Wv   = (const float*)d_in[6];
    const float* bv   = (const float*)d_in[7];
    const float* Wo   = (const float*)d_in[8];
    const float* bo   = (const float*)d_in[9];

    float* outp = (float*)d_out;

    half *ahp, *qfp, *kfp, *vfp, *chp, *clp, *wqp, *wkp, *wvp, *wop;
    cudaGetSymbolAddress((void**)&ahp, g_ah);
    cudaGetSymbolAddress((void**)&qfp, g_qf);
    cudaGetSymbolAddress((void**)&kfp, g_kf);
    cudaGetSymbolAddress((void**)&vfp, g_vf);
    cudaGetSymbolAddress((void**)&chp, g_ch);
    cudaGetSymbolAddress((void**)&clp, g_cl);
    cudaGetSymbolAddress((void**)&wqp, g_wq);
    cudaGetSymbolAddress((void**)&wkp, g_wk);
    cudaGetSymbolAddress((void**)&wvp, g_wv);
    cudaGetSymbolAddress((void**)&wop, g_wo);

    float* attnp = nullptr;
    if ((long long)out_size >= OUT_ELEMS + ATTN_ELEMS)
        attnp = outp + OUT_ELEMS;

    // 1. fused casts to fp16
    {
        int n = M_ * D_ + 4 * D_ * D_;
        cast_all_kernel<<<(n + 255) / 256, 256>>>(hs, Wq, Wk, Wv, Wo,
                                                  ahp, wqp, wkp, wvp, wop);
    }

    const int smem1 = 3 * 2 * 128 * 40 * (int)sizeof(half);   // 61440 (1-pass, 3 stages)
    const int smem2 = 2 * 3 * 128 * 40 * (int)sizeof(half);   // 61440 (2-pass, 2 stages)
    cudaFuncSetAttribute(gemm_mma_kernel<false>,
                         cudaFuncAttributeMaxDynamicSharedMemorySize, smem1);
    cudaFuncSetAttribute(gemm_mma_kernel<true>,
                         cudaFuncAttributeMaxDynamicSharedMemorySize, smem2);

    // 2. fused Q/K/V projections (1-pass fp16)
    {
        GemmArgs3 a3;
        a3.a[0] = {ahp, nullptr, wqp, bq, nullptr, qfp};
        a3.a[1] = {ahp, nullptr, wkp, bk, nullptr, kfp};
        a3.a[2] = {ahp, nullptr, wvp, bv, nullptr, vfp};
        dim3 gg(D_ / 128, M_ / 128, 3);
        gemm_mma_kernel<false><<<gg, 256, smem1>>>(a3);
    }

    // 3. two-phase fp16 attention
    {
        dim3 ga(S_ / 64, H_, B_);
        int smA = (4608 + 4 * 4608) * (int)sizeof(half)
                  + 2048 * (int)sizeof(int) + 64 * (int)sizeof(float);
        cudaFuncSetAttribute(attn_fp16_kernel,
                             cudaFuncAttributeMaxDynamicSharedMemorySize, smA);
        attn_fp16_kernel<<<ga, 256, smA>>>(qfp, kfp, vfp, mask, attnp, chp, clp);
    }

    // 4. output projection (2-pass: ctx hi + lo)
    {
        GemmArgs3 a3;
        a3.a[0] = {chp, clp, wop, bo, outp, nullptr};
        dim3 gg(D_ / 128, M_ / 128, 1);
        gemm_mma_kernel<true><<<gg, 256, smem2>>>(a3);
    }
}

// round 11
// speedup vs baseline: 2.3195x; 1.0510x over previous
#include <cuda_runtime.h>
#include <cuda_fp16.h>
#include <cstdint>

namespace {
constexpr int B_  = 4;
constexpr int S_  = 2048;
constexpr int D_  = 1024;
constexpr int H_  = 16;
constexpr int M_  = B_ * S_;  // 8192
constexpr long long OUT_ELEMS  = (long long)M_ * D_;
constexpr long long ATTN_ELEMS = (long long)B_ * H_ * S_ * S_;
}

// ------------------------- device scratch (no allocs) -----------------------
__device__ half g_ah[M_ * D_];
__device__ half g_qf[M_ * D_], g_kf[M_ * D_], g_vf[M_ * D_];
__device__ half g_ch[M_ * D_], g_cl[M_ * D_];
__device__ half g_wq[D_ * D_], g_wk[D_ * D_], g_wv[D_ * D_], g_wo[D_ * D_];

// ----------------------------- helpers --------------------------------------
__device__ __forceinline__ uint32_t smem_u32(const void* p) {
    uint32_t a;
    asm("{ .reg .u64 t; cvta.to.shared.u64 t, %1; cvt.u32.u64 %0, t; }"
        : "=r"(a) : "l"(p));
    return a;
}

__device__ __forceinline__ void cp16(uint32_t s, const void* g) {
    asm volatile("cp.async.cg.shared.global [%0], [%1], 16;" :: "r"(s), "l"(g));
}
#define CP_COMMIT asm volatile("cp.async.commit_group;" ::: "memory")
#define CP_WAIT0  asm volatile("cp.async.wait_group 0;" ::: "memory")
#define CP_WAIT1  asm volatile("cp.async.wait_group 1;" ::: "memory")

#define LDSM_X4(r0, r1, r2, r3, addr) \
    asm volatile("ldmatrix.sync.aligned.m8n8.x4.shared.b16 {%0,%1,%2,%3}, [%4];" \
                 : "=r"(r0), "=r"(r1), "=r"(r2), "=r"(r3) : "r"(addr))

#define LDSM_X4T(r0, r1, r2, r3, addr) \
    asm volatile("ldmatrix.sync.aligned.m8n8.x4.trans.shared.b16 {%0,%1,%2,%3}, [%4];" \
                 : "=r"(r0), "=r"(r1), "=r"(r2), "=r"(r3) : "r"(addr))

__device__ __forceinline__ void mma_hf(float c[4], const uint32_t a[4],
                                       uint32_t b0, uint32_t b1) {
    asm volatile(
        "mma.sync.aligned.m16n8k16.row.col.f32.f16.f16.f32 "
        "{%0,%1,%2,%3}, {%4,%5,%6,%7}, {%8,%9}, {%0,%1,%2,%3};"
        : "+f"(c[0]), "+f"(c[1]), "+f"(c[2]), "+f"(c[3])
        : "r"(a[0]), "r"(a[1]), "r"(a[2]), "r"(a[3]), "r"(b0), "r"(b1));
}

__device__ __forceinline__ uint32_t pack2h(float x, float y) {
    __half2 t = __floats2half2_rn(x, y);
    return *reinterpret_cast<uint32_t*>(&t);
}

// ---------------------------------------------------------------------------
// Fused fp32 -> fp16 cast of hidden_states + 4 weight matrices.
// ---------------------------------------------------------------------------
__global__ void cast_all_kernel(const float* __restrict__ hs,
                                const float* __restrict__ Wq,
                                const float* __restrict__ Wk,
                                const float* __restrict__ Wv,
                                const float* __restrict__ Wo,
                                half* __restrict__ ah,
                                half* __restrict__ wq, half* __restrict__ wk,
                                half* __restrict__ wv, half* __restrict__ wo)
{
    int i = blockIdx.x * blockDim.x + threadIdx.x;
    constexpr int MD = M_ * D_;           // 2^23
    constexpr int DD = D_ * D_;           // 2^20
    if (i < MD) {
        ah[i] = __float2half_rn(hs[i]);
    } else {
        int j = i - MD;
        int wsel = j >> 20;
        int off = j & (DD - 1);
        const float* src = (wsel == 0) ? Wq : (wsel == 1) ? Wk
                         : (wsel == 2) ? Wv : Wo;
        half* dst = (wsel == 0) ? wq : (wsel == 1) ? wk
                  : (wsel == 2) ? wv : wo;
        dst[off] = __float2half_rn(src[off]);
    }
}

// ---------------------------------------------------------------------------
// fp16 HMMA GEMM: C = (Ahi [+ Alo]) @ Wh^T + bias.
// ---------------------------------------------------------------------------
struct GemmArgs {
    const half *Ahi, *Alo, *Wh;
    const float* bias;
    float* Cf;
    half* Cq;
};
struct GemmArgs3 { GemmArgs a[3]; };

template <bool TWO>
__global__ void __launch_bounds__(256, 2) gemm_mma_kernel(GemmArgs3 args)
{
    constexpr int PA = 40;
    constexpr int BUFE = 128 * PA;              // 5120 halves per sub-tile
    constexpr int NB = TWO ? 3 : 2;             // bufs per stage
    constexpr int STAGE = NB * BUFE;
    extern __shared__ __align__(16) half gsm[];

    const GemmArgs ga = args.a[blockIdx.z];

    const int tid = threadIdx.x;
    const int w = tid >> 5, lane = tid & 31, gid = lane >> 2, tig = lane & 3;
    const int bm = blockIdx.y * 128, bn = blockIdx.x * 128;
    const int m0 = (w >> 1) * 32, n0 = (w & 1) * 64;

    float c[2][8][4] = {};

    auto load_chunk = [&](int t, int buf) {
        int kc = t << 5;
        half* sAh = gsm + buf * STAGE;
        half* sW  = sAh + (NB - 1) * BUFE;
#pragma unroll
        for (int i = 0; i < 2; ++i) {
            int idx = tid * 2 + i;           // 0..511
            int row = idx >> 2, q = idx & 3;
            size_t go = (size_t)row * 1024 + kc + q * 8;
            cp16(smem_u32(&sAh[row * PA + q * 8]), ga.Ahi + (size_t)bm * 1024 + go);
            if (TWO)
                cp16(smem_u32(&sAh[BUFE + row * PA + q * 8]),
                     ga.Alo + (size_t)bm * 1024 + go);
            cp16(smem_u32(&sW[row * PA + q * 8]), ga.Wh + (size_t)bn * 1024 + go);
        }
    };

    auto compute_chunk = [&](int buf) {
        const half* sAh = gsm + buf * STAGE;
        const half* sAl = sAh + BUFE;
        const half* sW  = sAh + (NB - 1) * BUFE;
#pragma unroll
        for (int ks = 0; ks < 32; ks += 16) {
            uint32_t ah[2][4], al[2][4];
#pragma unroll
            for (int mi = 0; mi < 2; ++mi) {
                int ro = (m0 + mi * 16 + (lane & 15)) * PA + ks + ((lane >> 4) << 3);
                LDSM_X4(ah[mi][0], ah[mi][1], ah[mi][2], ah[mi][3], smem_u32(&sAh[ro]));
                if (TWO)
                    LDSM_X4(al[mi][0], al[mi][1], al[mi][2], al[mi][3],
                            smem_u32(&sAl[ro]));
            }
#pragma unroll
            for (int p = 0; p < 4; ++p) {
                int br = n0 + p * 16 + (lane & 7) + ((lane >> 4) << 3);
                int bc = ks + (((lane >> 3) & 1) << 3);
                uint32_t b0, b1, b2, b3;
                LDSM_X4(b0, b1, b2, b3, smem_u32(&sW[br * PA + bc]));
                mma_hf(c[0][2 * p],     ah[0], b0, b1);
                mma_hf(c[1][2 * p],     ah[1], b0, b1);
                mma_hf(c[0][2 * p + 1], ah[0], b2, b3);
                mma_hf(c[1][2 * p + 1], ah[1], b2, b3);
                if (TWO) {
                    mma_hf(c[0][2 * p],     al[0], b0, b1);
                    mma_hf(c[1][2 * p],     al[1], b0, b1);
                    mma_hf(c[0][2 * p + 1], al[0], b2, b3);
                    mma_hf(c[1][2 * p + 1], al[1], b2, b3);
                }
            }
        }
    };

    load_chunk(0, 0); CP_COMMIT;
    load_chunk(1, 1); CP_COMMIT;

    if (TWO) {
        for (int t = 0; t < 32; ++t) {
            if (t + 2 < 32) { CP_WAIT1; } else { CP_WAIT0; }
            __syncthreads();
            compute_chunk(t & 1);
            __syncthreads();
            if (t + 2 < 32) { load_chunk(t + 2, t & 1); CP_COMMIT; }
        }
    } else {
        for (int t = 0; t < 32; ++t) {
            if (t + 2 < 32) { CP_WAIT1; } else { CP_WAIT0; }
            __syncthreads();
            if (t + 2 < 32) { load_chunk(t + 2, (t + 2) % 3); CP_COMMIT; }
            compute_chunk(t % 3);
            __syncthreads();
        }
    }

#pragma unroll
    for (int mi = 0; mi < 2; ++mi) {
#pragma unroll
        for (int ni = 0; ni < 8; ++ni) {
            int r0 = bm + m0 + mi * 16 + gid;
            int col = bn + n0 + ni * 8 + 2 * tig;
            float bv0 = ga.bias[col], bv1 = ga.bias[col + 1];
            float o00 = c[mi][ni][0] + bv0, o01 = c[mi][ni][1] + bv1;
            float o10 = c[mi][ni][2] + bv0, o11 = c[mi][ni][3] + bv1;
            if (ga.Cf) {
                *(float2*)&ga.Cf[(size_t)r0 * 1024 + col] = make_float2(o00, o01);
                *(float2*)&ga.Cf[(size_t)(r0 + 8) * 1024 + col] = make_float2(o10, o11);
            }
            if (ga.Cq) {
                *(uint32_t*)&ga.Cq[(size_t)r0 * 1024 + col]       = pack2h(o00, o01);
                *(uint32_t*)&ga.Cq[(size_t)(r0 + 8) * 1024 + col] = pack2h(o10, o11);
            }
        }
    }
}

// ---------------------------------------------------------------------------
// Two-phase fp16 flash attention.
//   q-tile 64/CTA; 8 warps = 4 q-groups (16 rows) x 2 key-halves (32 keys).
//   3-stage K/V ring (ONE __syncthreads per chunk); launch_bounds(256,3).
// ---------------------------------------------------------------------------
__global__ void __launch_bounds__(256, 3) attn_fp16_kernel(
    const half* __restrict__ qf, const half* __restrict__ kf,
    const half* __restrict__ vf, const int* __restrict__ maskg,
    float* __restrict__ attn,
    half* __restrict__ ctxh, half* __restrict__ ctxl)
{
    constexpr int P = 72;
    constexpr int KTILE = 64 * P;        // 4608 halves
    constexpr int STAGE = 2 * KTILE;     // K + V per ring stage
    constexpr int CTXP = 66;             // sCtx pitch (floats)
    extern __shared__ __align__(16) half hsm[];
    half* Qs  = hsm;                     // 64*72 = 4608 halves
    half* KV0 = hsm + 4608;              // 3 ring stages x (K,V)
    int*  sMask = (int*)(hsm + 4608 + 3 * STAGE);   // 2048 ints
    float* sL   = (float*)(sMask + 2048);           // 64 floats
    float* sCtx = (float*)KV0;           // aliases ring (post-loop)

    const int tid = threadIdx.x;
    const int w = tid >> 5, lane = tid & 31, gid = lane >> 2, tig = lane & 3;
    const int qt = blockIdx.x, h = blockIdx.y, b = blockIdx.z;
    const int q0 = qt * 64;
    const int qg = w >> 1, kh = w & 1;
    const int m0 = qg * 16;
    const int n0k = kh * 32;

    if (tid < 64) sL[tid] = 0.f;

    // ---- Q (64x64) + full mask row (one commit group) ----
    {
        size_t base = (size_t)(b * S_ + q0) * D_ + h * 64;
#pragma unroll
        for (int i = 0; i < 2; ++i) {
            int idx = tid * 2 + i;
            int row = idx >> 3, qq = idx & 7;
            cp16(smem_u32(&Qs[row * P + qq * 8]), qf + base + (size_t)row * D_ + qq * 8);
        }
#pragma unroll
        for (int i = 0; i < 2; ++i) {
            int j = tid * 2 + i;
            cp16(smem_u32(&sMask[j * 4]), maskg + b * S_ + j * 4);
        }
        CP_COMMIT;
    }

    auto load_k = [&](int kt, int st) {
        size_t kbase = (size_t)(b * S_ + kt * 64) * D_ + h * 64;
        half* Ks_ = KV0 + st * STAGE;
#pragma unroll
        for (int i = 0; i < 2; ++i) {
            int idx = tid * 2 + i;
            int row = idx >> 3, qq = idx & 7;
            cp16(smem_u32(&Ks_[row * P + qq * 8]), kf + kbase + (size_t)row * D_ + qq * 8);
        }
    };
    auto load_kv = [&](int kt, int st) {
        size_t kbase = (size_t)(b * S_ + kt * 64) * D_ + h * 64;
        half* Ks_ = KV0 + st * STAGE;
        half* Vs_ = Ks_ + KTILE;
#pragma unroll
        for (int i = 0; i < 2; ++i) {
            int idx = tid * 2 + i;
            int row = idx >> 3, qq = idx & 7;
            size_t go = kbase + (size_t)row * D_ + qq * 8;
            cp16(smem_u32(&Ks_[row * P + qq * 8]), kf + go);
            cp16(smem_u32(&Vs_[row * P + qq * 8]), vf + go);
        }
    };

    auto computeS = [&](const half* Ks_, float sc[4][4]) {
#pragma unroll
        for (int ks = 0; ks < 64; ks += 16) {
            uint32_t a[4];
            LDSM_X4(a[0], a[1], a[2], a[3],
                    smem_u32(&Qs[(m0 + (lane & 15)) * P + ks + ((lane >> 4) << 3)]));
#pragma unroll
            for (int p = 0; p < 2; ++p) {
                int br = n0k + p * 16 + (lane & 7) + ((lane >> 4) << 3);
                int bc = ks + (((lane >> 3) & 1) << 3);
                uint32_t b0, b1, b2, b3;
                LDSM_X4(b0, b1, b2, b3, smem_u32(&Ks_[br * P + bc]));
                mma_hf(sc[2 * p],     a, b0, b1);
                mma_hf(sc[2 * p + 1], a, b2, b3);
            }
        }
    };

    // ================= phase 1: l =================
    load_k(0, 0); CP_COMMIT;
    load_k(1, 1); CP_COMMIT;
    float lacc[2] = {};

    for (int kt = 0; kt < 32; ++kt) {
        if (kt < 31) { CP_WAIT1; } else { CP_WAIT0; }
        __syncthreads();
        if (kt + 2 < 32) { load_k(kt + 2, (kt + 2) % 3); CP_COMMIT; }

        float sc[4][4] = {};
        computeS(KV0 + (kt % 3) * STAGE, sc);

        const int* mk = sMask + kt * 64;
#pragma unroll
        for (int ni = 0; ni < 4; ++ni) {
            int cc = n0k + ni * 8 + 2 * tig;
            bool k0m = mk[cc] != 0, k1m = mk[cc + 1] != 0;
            lacc[0] += (k0m ? __expf(sc[ni][0] * 0.125f) : 0.f)
                     + (k1m ? __expf(sc[ni][1] * 0.125f) : 0.f);
            lacc[1] += (k0m ? __expf(sc[ni][2] * 0.125f) : 0.f)
                     + (k1m ? __expf(sc[ni][3] * 0.125f) : 0.f);
        }
    }

#pragma unroll
    for (int hf = 0; hf < 2; ++hf) {
        float v = lacc[hf];
        v += __shfl_xor_sync(0xffffffffu, v, 1);
        v += __shfl_xor_sync(0xffffffffu, v, 2);
        if (tig == 0) atomicAdd(&sL[m0 + gid + hf * 8], v);
    }
    __syncthreads();   // also guards ring reuse by phase-2 prologue

    float invl[2];
#pragma unroll
    for (int hf = 0; hf < 2; ++hf) {
        float lv = sL[m0 + gid + hf * 8];
        invl[hf] = (lv > 0.f) ? (1.f / lv) : 0.f;
    }

    // ================= phase 2: attn + ctx =================
    load_kv(0, 0); CP_COMMIT;
    load_kv(1, 1); CP_COMMIT;

    float ctxc[8][4] = {};

    for (int kt = 0; kt < 32; ++kt) {
        if (kt < 31) { CP_WAIT1; } else { CP_WAIT0; }
        __syncthreads();
        if (kt + 2 < 32) { load_kv(kt + 2, (kt + 2) % 3); CP_COMMIT; }

        const half* Ks_ = KV0 + (kt % 3) * STAGE;
        const half* Vs_ = Ks_ + KTILE;

        float sc[4][4] = {};
        computeS(Ks_, sc);

        const int* mk = sMask + kt * 64;
        uint32_t ah[2][4];
#pragma unroll
        for (int ni = 0; ni < 4; ++ni) {
            int cc = n0k + ni * 8 + 2 * tig;
            bool k0m = mk[cc] != 0, k1m = mk[cc + 1] != 0;
            float p00 = k0m ? (__expf(sc[ni][0] * 0.125f) * invl[0]) : 0.f;
            float p01 = k1m ? (__expf(sc[ni][1] * 0.125f) * invl[0]) : 0.f;
            float p10 = k0m ? (__expf(sc[ni][2] * 0.125f) * invl[1]) : 0.f;
            float p11 = k1m ? (__expf(sc[ni][3] * 0.125f) * invl[1]) : 0.f;
            if (attn) {
                size_t arow = ((size_t)((b * H_ + h) * S_) + q0 + m0 + gid) * S_
                              + kt * 64 + cc;
                *(float2*)&attn[arow]                  = make_float2(p00, p01);
                *(float2*)&attn[arow + 8 * (size_t)S_] = make_float2(p10, p11);
            }
            int kt2 = ni >> 1, bse = (ni & 1) * 2;
            ah[kt2][bse]     = pack2h(p00, p01);
            ah[kt2][bse + 1] = pack2h(p10, p11);
        }

#pragma unroll
        for (int kt2 = 0; kt2 < 2; ++kt2)
#pragma unroll
            for (int nj = 0; nj < 8; nj += 2) {
                uint32_t b0, b1, b2, b3;
                LDSM_X4T(b0, b1, b2, b3,
                         smem_u32(&Vs_[(n0k + kt2 * 16 + (lane & 15)) * P
                                       + (nj + (lane >> 4)) * 8]));
                mma_hf(ctxc[nj],     ah[kt2], b0, b1);
                mma_hf(ctxc[nj + 1], ah[kt2], b2, b3);
            }
    }
    __syncthreads();   // all ring reads done before sCtx aliasing

    // ---- pair-sum ctx across key-halves, write fp16 hi/lo ----
    if (kh == 1) {
#pragma unroll
        for (int nj = 0; nj < 8; ++nj) {
            int r = m0 + gid;
            int cl = nj * 8 + 2 * tig;
            *(float2*)&sCtx[r * CTXP + cl] = make_float2(ctxc[nj][0], ctxc[nj][1]);
            *(float2*)&sCtx[(r + 8) * CTXP + cl] = make_float2(ctxc[nj][2], ctxc[nj][3]);
        }
    }
    __syncthreads();
    if (kh == 0) {
#pragma unroll
        for (int nj = 0; nj < 8; ++nj) {
            int rl = m0 + gid;
            int cl = nj * 8 + 2 * tig;
            float2 o0 = *(float2*)&sCtx[rl * CTXP + cl];
            float2 o1 = *(float2*)&sCtx[(rl + 8) * CTXP + cl];
            float v00 = ctxc[nj][0] + o0.x, v01 = ctxc[nj][1] + o0.y;
            float v10 = ctxc[nj][2] + o1.x, v11 = ctxc[nj][3] + o1.y;
            int r = q0 + rl;
            int col = h * 64 + cl;
            size_t base = ((size_t)(b * S_) + r) * D_ + col;
            float h00 = __half2float(__float2half_rn(v00));
            float h01 = __half2float(__float2half_rn(v01));
            float h10 = __half2float(__float2half_rn(v10));
            float h11 = __half2float(__float2half_rn(v11));
            *(uint32_t*)&ctxh[base]                  = pack2h(v00, v01);
            *(uint32_t*)&ctxh[base + 8 * (size_t)D_] = pack2h(v10, v11);
            *(uint32_t*)&ctxl[base]                  = pack2h(v00 - h00, v01 - h01);
            *(uint32_t*)&ctxl[base + 8 * (size_t)D_] = pack2h(v10 - h10, v11 - h11);
        }
    }
}

// ---------------------------------------------------------------------------
extern "C" void kernel_launch(void* const* d_in, const int* in_sizes, int n_in,
                              void* d_out, int out_size)
{
    const float* hs   = (const float*)d_in[0];
    const int*   mask = (const int*)  d_in[1];
    const float* Wq   = (const float*)d_in[2];
    const float* bq   = (const float*)d_in[3];
    const float* Wk   = (const float*)d_in[4];
    const float* bk   = (const float*)d_in[5];
    const float* Wv   = (const float*)d_in[6];
    const float* bv   = (const float*)d_in[7];
    const float* Wo   = (const float*)d_in[8];
    const float* bo   = (const float*)d_in[9];

    float* outp = (float*)d_out;

    half *ahp, *qfp, *kfp, *vfp, *chp, *clp, *wqp, *wkp, *wvp, *wop;
    cudaGetSymbolAddress((void**)&ahp, g_ah);
    cudaGetSymbolAddress((void**)&qfp, g_qf);
    cudaGetSymbolAddress((void**)&kfp, g_kf);
    cudaGetSymbolAddress((void**)&vfp, g_vf);
    cudaGetSymbolAddress((void**)&chp, g_ch);
    cudaGetSymbolAddress((void**)&clp, g_cl);
    cudaGetSymbolAddress((void**)&wqp, g_wq);
    cudaGetSymbolAddress((void**)&wkp, g_wk);
    cudaGetSymbolAddress((void**)&wvp, g_wv);
    cudaGetSymbolAddress((void**)&wop, g_wo);

    float* attnp = nullptr;
    if ((long long)out_size >= OUT_ELEMS + ATTN_ELEMS)
        attnp = outp + OUT_ELEMS;

    // 1. fused casts to fp16
    {
        int n = M_ * D_ + 4 * D_ * D_;
        cast_all_kernel<<<(n + 255) / 256, 256>>>(hs, Wq, Wk, Wv, Wo,
                                                  ahp, wqp, wkp, wvp, wop);
    }

    const int smem1 = 3 * 2 * 128 * 40 * (int)sizeof(half);   // 61440
    const int smem2 = 2 * 3 * 128 * 40 * (int)sizeof(half);   // 61440
    cudaFuncSetAttribute(gemm_mma_kernel<false>,
                         cudaFuncAttributeMaxDynamicSharedMemorySize, smem1);
    cudaFuncSetAttribute(gemm_mma_kernel<true>,
                         cudaFuncAttributeMaxDynamicSharedMemorySize, smem2);

    // 2. fused Q/K/V projections (1-pass fp16)
    {
        GemmArgs3 a3;
        a3.a[0] = {ahp, nullptr, wqp, bq, nullptr, qfp};
        a3.a[1] = {ahp, nullptr, wkp, bk, nullptr, kfp};
        a3.a[2] = {ahp, nullptr, wvp, bv, nullptr, vfp};
        dim3 gg(D_ / 128, M_ / 128, 3);
        gemm_mma_kernel<false><<<gg, 256, smem1>>>(a3);
    }

    // 3. two-phase fp16 attention (3-stage ring; 3 CTAs/SM target)
    {
        dim3 ga(S_ / 64, H_, B_);
        int smA = (4608 + 3 * 2 * 4608) * (int)sizeof(half)
                  + 2048 * (int)sizeof(int) + 64 * (int)sizeof(float);  // 72960
        cudaFuncSetAttribute(attn_fp16_kernel,
                             cudaFuncAttributeMaxDynamicSharedMemorySize, smA);
        attn_fp16_kernel<<<ga, 256, smA>>>(qfp, kfp, vfp, mask, attnp, chp, clp);
    }

    // 4. output projection (2-pass: ctx hi + lo)
    {
        GemmArgs3 a3;
        a3.a[0] = {chp, clp, wop, bo, outp, nullptr};
        dim3 gg(D_ / 128, M_ / 128, 1);
        gemm_mma_kernel<true><<<gg, 256, smem2>>>(a3);
    }
}